// round 4
// baseline (speedup 1.0000x reference)
#include <cuda_runtime.h>
#include <cuda_bf16.h>

#define BB   32
#define NEX  1024
#define NKC  128
#define DH   64

// ---------------- scratch (device globals, 16B-aligned for float4) ---------
__device__ __align__(16) float g_x[BB * 64];
__device__ __align__(16) float g_kci[BB * NKC];
__device__ __align__(16) float g_kcg[NKC * NKC];
__device__ __align__(16) float g_epart[NKC * 64];
__device__ __align__(16) float g_newh[BB * NKC * 64];
__device__ __align__(16) float g_dpart[BB * NKC * 64];
__device__ __align__(16) float g_twihT[64 * 192];
__device__ __align__(16) float g_twhhT[64 * 192];
__device__ __align__(16) float g_WdhT[64 * 64];
__device__ __align__(16) float g_ulinT[64 * 64];
__device__ __align__(16) float g_uwihT[64 * 192];
__device__ __align__(16) float g_uwhhT[64 * 192];

__device__ __forceinline__ float sigf(float v)     { return 1.f / (1.f + __expf(-v)); }
__device__ __forceinline__ float tanhfast(float v) { return 2.f / (1.f + __expf(-2.f * v)) - 1.f; }

// ---------------- K0: precompute ------------------------------------------
// blocks 0..31  : x[b] (block per b, smem-staged ex row, float4)
// blocks 32..63 : kci[b] (block per b, float4 over j)
// blocks 64..71 : kcg = sigmoid(kc_gamma)
// block  72     : epart
// blocks 73..88 : weight transposes
__global__ void __launch_bounds__(256) k0(
    const float* __restrict__ ex, const float* __restrict__ su,
    const float* __restrict__ ex_graph, const float* __restrict__ kc_gamma,
    const float* __restrict__ W_ex, const float* __restrict__ W_kc,
    const float* __restrict__ tgru_wih, const float* __restrict__ tgru_whh,
    const float* __restrict__ fpart_w, const float* __restrict__ fpart_b,
    const float* __restrict__ ulin_w,
    const float* __restrict__ ugru_wih, const float* __restrict__ ugru_whh)
{
    __shared__ float sbuf[4160];
    int blk = blockIdx.x, tid = threadIdx.x;

    if (blk < 32) {
        // x[b,e] = su*dot(ex[b], W[e,0:1024]) + (1-su)*dot(ex[b], W[e,1024:2048])
        int b = blk;
        float4* ex_s4 = (float4*)sbuf;
        ex_s4[tid] = ((const float4*)(ex + b * 1024))[tid];
        __syncthreads();
        int warp = tid >> 5, lane = tid & 31;
        float s = su[b];
        #pragma unroll
        for (int q = 0; q < 8; q++) {
            int e = warp * 8 + q;
            const float4* w4 = (const float4*)(W_ex + e * 2048);
            float a1 = 0.f, a2 = 0.f;
            #pragma unroll
            for (int it = 0; it < 8; it++) {
                int idx = it * 32 + lane;
                float4 ev = ex_s4[idx];
                float4 wa = w4[idx];
                float4 wb = w4[idx + 256];
                a1 = fmaf(ev.x, wa.x, fmaf(ev.y, wa.y, fmaf(ev.z, wa.z, fmaf(ev.w, wa.w, a1))));
                a2 = fmaf(ev.x, wb.x, fmaf(ev.y, wb.y, fmaf(ev.z, wb.z, fmaf(ev.w, wb.w, a2))));
            }
            #pragma unroll
            for (int o = 16; o; o >>= 1) {
                a1 += __shfl_xor_sync(0xffffffffu, a1, o);
                a2 += __shfl_xor_sync(0xffffffffu, a2, o);
            }
            if (lane == 0) g_x[b * 64 + e] = s * a1 + (1.f - s) * a2;
        }
    } else if (blk < 64) {
        // kci[b,:] = ex[b] @ ex_graph   (float4 over j, 8 n-slices, smem reduce)
        int b = blk - 32;
        ((float4*)sbuf)[tid] = ((const float4*)(ex + b * 1024))[tid];
        __syncthreads();
        int j4 = tid & 31, ns = tid >> 5;
        float4 acc = make_float4(0.f, 0.f, 0.f, 0.f);
        const float4* eg4 = (const float4*)ex_graph;
        int n0 = ns * 128;
        #pragma unroll 4
        for (int n = n0; n < n0 + 128; n++) {
            float ev = sbuf[n];
            float4 gv = eg4[n * 32 + j4];
            acc.x = fmaf(ev, gv.x, acc.x);
            acc.y = fmaf(ev, gv.y, acc.y);
            acc.z = fmaf(ev, gv.z, acc.z);
            acc.w = fmaf(ev, gv.w, acc.w);
        }
        __syncthreads();
        ((float4*)(sbuf + 1024))[ns * 32 + j4] = acc;
        __syncthreads();
        if (tid < 128) {
            float sacc = 0.f;
            #pragma unroll
            for (int k = 0; k < 8; k++) sacc += sbuf[1024 + k * 128 + tid];
            g_kci[b * 128 + tid] = sacc;
        }
    } else if (blk < 72) {
        int base = (blk - 64) * 2048;
        for (int i = tid; i < 2048; i += 256)
            g_kcg[base + i] = sigf(kc_gamma[base + i]);
    } else if (blk == 72) {
        // epart[j][d] = fpart_b[d] + sum_k W_kc[k,j] * fpart_w[d, 64+k]
        for (int i = tid; i < 64 * 64; i += 256) {
            int dd = i >> 6, k = i & 63;
            sbuf[dd * 65 + k] = fpart_w[dd * 128 + 64 + k];
        }
        __syncthreads();
        for (int i = tid; i < NKC * 64; i += 256) {
            int j = i >> 6, d = i & 63;
            float acc = fpart_b[d];
            #pragma unroll 8
            for (int k = 0; k < 64; k++)
                acc = fmaf(W_kc[k * 128 + j], sbuf[d * 65 + k], acc);
            g_epart[i] = acc;
        }
    } else {
        int idx0 = (blk - 73) * 3584;
        for (int c = 0; c < 3584; c += 256) {
            int idx = idx0 + c + tid;
            if (idx < 12288)      { int k = idx / 192, t = idx % 192; g_twihT[idx] = tgru_wih[t * 64 + k]; }
            else if (idx < 24576) { int r = idx - 12288; int k = r / 192, t = r % 192; g_twhhT[r] = tgru_whh[t * 64 + k]; }
            else if (idx < 36864) { int r = idx - 24576; int k = r / 192, t = r % 192; g_uwihT[r] = ugru_wih[t * 64 + k]; }
            else if (idx < 49152) { int r = idx - 36864; int k = r / 192, t = r % 192; g_uwhhT[r] = ugru_whh[t * 64 + k]; }
            else if (idx < 53248) { int r = idx - 49152; int k = r >> 6, d = r & 63;  g_WdhT[r]  = fpart_w[d * 128 + k]; }
            else                  { int r = idx - 53248; int k = r >> 6, d = r & 63;  g_ulinT[r] = ulin_w[d * 64 + k]; }
        }
    }
}

// ---------------- K2: git + th-GRU + new_h + dpart (16 rows/block, float4) --
// 256 threads = 16 rows (l) x 16 d4. 256 blocks, one b per block.
__global__ void __launch_bounds__(256) k2(
    const float* __restrict__ h, const float* __restrict__ tgru_bih,
    const float* __restrict__ tgru_bhh)
{
    __shared__ float x_s[64];
    __shared__ float git_s[192];
    __shared__ float h_s[16][64];
    __shared__ float delta_s[16][64];

    int tid = threadIdx.x;
    int row0 = blockIdx.x * 16;
    int b = row0 >> 7;

    if (tid < 64) x_s[tid] = g_x[b * 64 + tid];
    ((float4*)h_s)[tid] = ((const float4*)(h + row0 * 64))[tid];
    __syncthreads();

    if (tid < 192) {
        float acc = tgru_bih[tid];
        #pragma unroll 8
        for (int k = 0; k < 64; k++)
            acc = fmaf(x_s[k], g_twihT[k * 192 + tid], acc);
        git_s[tid] = acc;
    }

    int l = tid >> 4, d4 = tid & 15;
    int row = row0 + l;
    const float4* bhh4 = (const float4*)tgru_bhh;
    float4 ar = bhh4[d4], az = bhh4[16 + d4], an = bhh4[32 + d4];
    const float4* whh4 = (const float4*)g_twhhT;
    __syncthreads();

    #pragma unroll 8
    for (int k = 0; k < 64; k++) {
        float hk = h_s[l][k];
        float4 wr = whh4[k * 48 + d4];
        float4 wz = whh4[k * 48 + 16 + d4];
        float4 wn = whh4[k * 48 + 32 + d4];
        ar.x = fmaf(hk, wr.x, ar.x); ar.y = fmaf(hk, wr.y, ar.y);
        ar.z = fmaf(hk, wr.z, ar.z); ar.w = fmaf(hk, wr.w, ar.w);
        az.x = fmaf(hk, wz.x, az.x); az.y = fmaf(hk, wz.y, az.y);
        az.z = fmaf(hk, wz.z, az.z); az.w = fmaf(hk, wz.w, az.w);
        an.x = fmaf(hk, wn.x, an.x); an.y = fmaf(hk, wn.y, an.y);
        an.z = fmaf(hk, wn.z, an.z); an.w = fmaf(hk, wn.w, an.w);
    }

    float kciv = g_kci[row];
    float4 hv  = ((const float4*)h_s[l])[d4];
    float4 gir = ((const float4*)git_s)[d4];
    float4 giz = ((const float4*)git_s)[16 + d4];
    float4 gin = ((const float4*)git_s)[32 + d4];

    float4 nh4, dl4;
    {
        float r0 = sigf(gir.x + ar.x), z0 = sigf(giz.x + az.x);
        float n0 = tanhfast(gin.x + r0 * an.x);
        float th = (1.f - z0) * n0 + z0 * hv.x;
        dl4.x = kciv * (th - hv.x); nh4.x = hv.x + dl4.x;
    }
    {
        float r0 = sigf(gir.y + ar.y), z0 = sigf(giz.y + az.y);
        float n0 = tanhfast(gin.y + r0 * an.y);
        float th = (1.f - z0) * n0 + z0 * hv.y;
        dl4.y = kciv * (th - hv.y); nh4.y = hv.y + dl4.y;
    }
    {
        float r0 = sigf(gir.z + ar.z), z0 = sigf(giz.z + az.z);
        float n0 = tanhfast(gin.z + r0 * an.z);
        float th = (1.f - z0) * n0 + z0 * hv.z;
        dl4.z = kciv * (th - hv.z); nh4.z = hv.z + dl4.z;
    }
    {
        float r0 = sigf(gir.w + ar.w), z0 = sigf(giz.w + az.w);
        float n0 = tanhfast(gin.w + r0 * an.w);
        float th = (1.f - z0) * n0 + z0 * hv.w;
        dl4.w = kciv * (th - hv.w); nh4.w = hv.w + dl4.w;
    }
    ((float4*)(g_newh + row * 64))[d4] = nh4;
    ((float4*)delta_s[l])[d4] = dl4;
    __syncthreads();

    float4 acc = make_float4(0.f, 0.f, 0.f, 0.f);
    const float4* wdh4 = (const float4*)g_WdhT;
    #pragma unroll 8
    for (int k = 0; k < 64; k++) {
        float dv = delta_s[l][k];
        float4 w = wdh4[k * 16 + d4];
        acc.x = fmaf(dv, w.x, acc.x); acc.y = fmaf(dv, w.y, acc.y);
        acc.z = fmaf(dv, w.z, acc.z); acc.w = fmaf(dv, w.w, acc.w);
    }
    ((float4*)(g_dpart + row * 64))[d4] = acc;
}

// ---------------- K3: partj reduce + ulin + u-GRU + output (float4) --------
// grid (8 jtiles, 32 b), 256 threads = 16 jl x 16 d4
__global__ void __launch_bounds__(256) k3(
    const float* __restrict__ ugru_bih, const float* __restrict__ ugru_bhh,
    const float* __restrict__ ulin_b, float* __restrict__ out)
{
    __shared__ __align__(16) float sm[10240];        // 40KB
    float4* dpart4 = (float4*)sm;                    // [128][16] float4
    float*  kcgw   = sm + 8192;                      // [128][16]
    // phase-2 aliases
    float (*partj_s)[64] = (float(*)[64])sm;         // [16][64]
    float (*outj_s)[64]  = (float(*)[64])(sm + 1024);
    float (*newh_s)[64]  = (float(*)[64])(sm + 2048);

    int jt = blockIdx.x, b = blockIdx.y;
    int tid = threadIdx.x;
    int jl = tid >> 4, d4 = tid & 15;
    int j = jt * 16 + jl;

    const float4* dp4 = (const float4*)(g_dpart + b * (NKC * 64));
    #pragma unroll
    for (int c = 0; c < 8; c++)
        dpart4[c * 256 + tid] = dp4[c * 256 + tid];
    #pragma unroll
    for (int c = 0; c < 8; c++) {
        int idx = c * 256 + tid;
        int ii = idx >> 4, jj = idx & 15;
        kcgw[idx] = g_kcg[ii * 128 + jt * 16 + jj] * g_kci[b * 128 + ii];
    }
    float4 ep = ((const float4*)g_epart)[j * 16 + d4];
    __syncthreads();

    // partj[b,j,d] = sum_i relu(dpart[i][d]+epart[j][d]) * kcgw[i][jl];  kcj = sum kcgw
    float4 acc = make_float4(0.f, 0.f, 0.f, 0.f);
    float wk = 0.f;
    #pragma unroll 8
    for (int i = 0; i < NKC; i++) {
        float wv = kcgw[i * 16 + jl];
        float4 p = dpart4[i * 16 + d4];
        acc.x = fmaf(fmaxf(p.x + ep.x, 0.f), wv, acc.x);
        acc.y = fmaf(fmaxf(p.y + ep.y, 0.f), wv, acc.y);
        acc.z = fmaf(fmaxf(p.z + ep.z, 0.f), wv, acc.z);
        acc.w = fmaf(fmaxf(p.w + ep.w, 0.f), wv, acc.w);
        wk += wv;
    }
    __syncthreads();   // phase-1 smem dead

    ((float4*)partj_s[jl])[d4] = acc;
    float4 nh4 = ((const float4*)g_newh)[(b * 128 + j) * 16 + d4];
    ((float4*)newh_s[jl])[d4] = nh4;
    __syncthreads();

    // outj = relu(partj @ ulin_w.T + ulin_b)
    const float4* ul4 = (const float4*)g_ulinT;
    float4 o = ((const float4*)ulin_b)[d4];
    #pragma unroll 8
    for (int k = 0; k < 64; k++) {
        float pv = partj_s[jl][k];
        float4 w = ul4[k * 16 + d4];
        o.x = fmaf(pv, w.x, o.x); o.y = fmaf(pv, w.y, o.y);
        o.z = fmaf(pv, w.z, o.z); o.w = fmaf(pv, w.w, o.w);
    }
    o.x = fmaxf(o.x, 0.f); o.y = fmaxf(o.y, 0.f);
    o.z = fmaxf(o.z, 0.f); o.w = fmaxf(o.w, 0.f);
    ((float4*)outj_s[jl])[d4] = o;
    __syncthreads();

    // u-GRU
    const float4* bih4 = (const float4*)ugru_bih;
    const float4* bhh4 = (const float4*)ugru_bhh;
    float4 gr = bih4[d4], gz = bih4[16 + d4], gn = bih4[32 + d4];
    float4 hr = bhh4[d4], hz = bhh4[16 + d4], hn = bhh4[32 + d4];
    const float4* wih4 = (const float4*)g_uwihT;
    const float4* whh4 = (const float4*)g_uwhhT;
    #pragma unroll 4
    for (int k = 0; k < 64; k++) {
        float ok = outj_s[jl][k];
        float nk = newh_s[jl][k];
        float4 wr = wih4[k * 48 + d4];
        float4 wz = wih4[k * 48 + 16 + d4];
        float4 wn = wih4[k * 48 + 32 + d4];
        float4 vr = whh4[k * 48 + d4];
        float4 vz = whh4[k * 48 + 16 + d4];
        float4 vn = whh4[k * 48 + 32 + d4];
        gr.x = fmaf(ok, wr.x, gr.x); gr.y = fmaf(ok, wr.y, gr.y);
        gr.z = fmaf(ok, wr.z, gr.z); gr.w = fmaf(ok, wr.w, gr.w);
        gz.x = fmaf(ok, wz.x, gz.x); gz.y = fmaf(ok, wz.y, gz.y);
        gz.z = fmaf(ok, wz.z, gz.z); gz.w = fmaf(ok, wz.w, gz.w);
        gn.x = fmaf(ok, wn.x, gn.x); gn.y = fmaf(ok, wn.y, gn.y);
        gn.z = fmaf(ok, wn.z, gn.z); gn.w = fmaf(ok, wn.w, gn.w);
        hr.x = fmaf(nk, vr.x, hr.x); hr.y = fmaf(nk, vr.y, hr.y);
        hr.z = fmaf(nk, vr.z, hr.z); hr.w = fmaf(nk, vr.w, hr.w);
        hz.x = fmaf(nk, vz.x, hz.x); hz.y = fmaf(nk, vz.y, hz.y);
        hz.z = fmaf(nk, vz.z, hz.z); hz.w = fmaf(nk, vz.w, hz.w);
        hn.x = fmaf(nk, vn.x, hn.x); hn.y = fmaf(nk, vn.y, hn.y);
        hn.z = fmaf(nk, vn.z, hn.z); hn.w = fmaf(nk, vn.w, hn.w);
    }

    float4 res;
    {
        float r0 = sigf(gr.x + hr.x), z0 = sigf(gz.x + hz.x);
        float n0 = tanhfast(gn.x + r0 * hn.x);
        float uh = (1.f - z0) * n0 + z0 * nh4.x;
        res.x = nh4.x + wk * (uh - nh4.x);
    }
    {
        float r0 = sigf(gr.y + hr.y), z0 = sigf(gz.y + hz.y);
        float n0 = tanhfast(gn.y + r0 * hn.y);
        float uh = (1.f - z0) * n0 + z0 * nh4.y;
        res.y = nh4.y + wk * (uh - nh4.y);
    }
    {
        float r0 = sigf(gr.z + hr.z), z0 = sigf(gz.z + hz.z);
        float n0 = tanhfast(gn.z + r0 * hn.z);
        float uh = (1.f - z0) * n0 + z0 * nh4.z;
        res.z = nh4.z + wk * (uh - nh4.z);
    }
    {
        float r0 = sigf(gr.w + hr.w), z0 = sigf(gz.w + hz.w);
        float n0 = tanhfast(gn.w + r0 * hn.w);
        float uh = (1.f - z0) * n0 + z0 * nh4.w;
        res.w = nh4.w + wk * (uh - nh4.w);
    }
    ((float4*)out)[(b * 128 + j) * 16 + d4] = res;
}

// ---------------- launch ----------------------------------------------------
extern "C" void kernel_launch(void* const* d_in, const int* in_sizes, int n_in,
                              void* d_out, int out_size)
{
    const float* h        = (const float*)d_in[0];
    const float* ex       = (const float*)d_in[1];
    const float* su       = (const float*)d_in[2];
    const float* ex_graph = (const float*)d_in[3];
    const float* kc_gamma = (const float*)d_in[4];
    const float* W_ex     = (const float*)d_in[5];
    const float* W_kc     = (const float*)d_in[6];
    const float* tgru_wih = (const float*)d_in[7];
    const float* tgru_whh = (const float*)d_in[8];
    const float* tgru_bih = (const float*)d_in[9];
    const float* tgru_bhh = (const float*)d_in[10];
    const float* fpart_w  = (const float*)d_in[11];
    const float* fpart_b  = (const float*)d_in[12];
    const float* ulin_w   = (const float*)d_in[13];
    const float* ulin_b   = (const float*)d_in[14];
    const float* ugru_wih = (const float*)d_in[15];
    const float* ugru_whh = (const float*)d_in[16];
    const float* ugru_bih = (const float*)d_in[17];
    const float* ugru_bhh = (const float*)d_in[18];
    float* out = (float*)d_out;

    k0<<<89, 256>>>(ex, su, ex_graph, kc_gamma, W_ex, W_kc,
                    tgru_wih, tgru_whh, fpart_w, fpart_b, ulin_w,
                    ugru_wih, ugru_whh);
    k2<<<256, 256>>>(h, tgru_bih, tgru_bhh);
    dim3 g3(8, 32);
    k3<<<g3, 256>>>(ugru_bih, ugru_bhh, ulin_b, out);
}

// round 5
// speedup vs baseline: 1.7902x; 1.7902x over previous
#include <cuda_runtime.h>
#include <cuda_bf16.h>

#define BB   32
#define NEX  1024
#define NKC  128
#define DH   64

// ---------------- scratch (device globals, 16B-aligned) --------------------
__device__ __align__(16) float g_x[BB * 64];
__device__ __align__(16) float g_kci[BB * NKC];
__device__ __align__(16) float g_kcg[NKC * NKC];
__device__ __align__(16) float g_epart[NKC * 64];
__device__ __align__(16) float g_newh[BB * NKC * 64];
__device__ __align__(16) float g_dpart[BB * NKC * 64];
__device__ __align__(16) float g_twihT[64 * 192];
__device__ __align__(16) float g_twhhT[64 * 192];
__device__ __align__(16) float g_WdhT[64 * 64];
__device__ __align__(16) float g_ulinT[64 * 64];
__device__ __align__(16) float g_uwihT[64 * 192];
__device__ __align__(16) float g_uwhhT[64 * 192];

__device__ __forceinline__ float sigf(float v)     { return 1.f / (1.f + __expf(-v)); }
__device__ __forceinline__ float tanhfast(float v) { return 2.f / (1.f + __expf(-2.f * v)) - 1.f; }

// ---------------- K0: precompute, 320 blocks x 256 -------------------------
// blocks   0..255 : x       (warp-per-output, 8 outputs/block)
// blocks 256..287 : kci     (block-per-b, 8 n-slices, MLP>=8)
// blocks 288..295 : kcg sigmoid
// blocks 296..303 : epart   (16 j-columns per block)
// blocks 304..319 : weight transposes (input-coalesced reads)
__global__ void __launch_bounds__(256) k0(
    const float* __restrict__ ex, const float* __restrict__ su,
    const float* __restrict__ ex_graph, const float* __restrict__ kc_gamma,
    const float* __restrict__ W_ex, const float* __restrict__ W_kc,
    const float* __restrict__ tgru_wih, const float* __restrict__ tgru_whh,
    const float* __restrict__ fpart_w, const float* __restrict__ fpart_b,
    const float* __restrict__ ulin_w,
    const float* __restrict__ ugru_wih, const float* __restrict__ ugru_whh)
{
    __shared__ __align__(16) float sbuf[4288];
    int blk = blockIdx.x, tid = threadIdx.x;

    if (blk < 256) {
        // x[b,e] = su*dot(ex[b], W[e,0:1024]) + (1-su)*dot(ex[b], W[e,1024:2048])
        // warp-per-output: 24 independent float4 loads, then reduce.
        int w = tid >> 5, lane = tid & 31;
        int oid = blk * 8 + w;                 // 0..2047
        int b = oid >> 6, e = oid & 63;
        const float4* W4  = (const float4*)W_ex + e * 512;
        const float4* ex4 = (const float4*)ex + b * 256;
        float a1 = 0.f, a2 = 0.f;
        #pragma unroll
        for (int it = 0; it < 8; it++) {
            int idx = it * 32 + lane;
            float4 ev = ex4[idx];
            float4 wa = W4[idx];
            float4 wb = W4[256 + idx];
            a1 = fmaf(ev.x, wa.x, fmaf(ev.y, wa.y, fmaf(ev.z, wa.z, fmaf(ev.w, wa.w, a1))));
            a2 = fmaf(ev.x, wb.x, fmaf(ev.y, wb.y, fmaf(ev.z, wb.z, fmaf(ev.w, wb.w, a2))));
        }
        #pragma unroll
        for (int o = 16; o; o >>= 1) {
            a1 += __shfl_xor_sync(0xffffffffu, a1, o);
            a2 += __shfl_xor_sync(0xffffffffu, a2, o);
        }
        if (lane == 0) {
            float s = su[b];
            g_x[oid] = s * a1 + (1.f - s) * a2;
        }
    } else if (blk < 288) {
        // kci[b,:] = ex[b] @ ex_graph. threads = (j4 0..31, ns 0..7); 128 n each.
        int b = blk - 256;
        float4* exs4 = (float4*)sbuf;                    // 256 float4 = ex row
        float*  red  = sbuf + 1024;                      // 8*128 partials
        exs4[tid] = ((const float4*)ex)[b * 256 + tid];
        __syncthreads();
        int j4 = tid & 31, ns = tid >> 5;
        const float4* eg4 = (const float4*)ex_graph;     // [n][32]
        float4 a0 = make_float4(0.f,0.f,0.f,0.f), a1 = make_float4(0.f,0.f,0.f,0.f);
        int n0 = ns * 128;
        #pragma unroll 4
        for (int n = n0; n < n0 + 128; n += 2) {
            float e0 = sbuf[n], e1 = sbuf[n + 1];
            float4 g0 = eg4[n * 32 + j4];
            float4 g1 = eg4[(n + 1) * 32 + j4];
            a0.x = fmaf(e0, g0.x, a0.x); a0.y = fmaf(e0, g0.y, a0.y);
            a0.z = fmaf(e0, g0.z, a0.z); a0.w = fmaf(e0, g0.w, a0.w);
            a1.x = fmaf(e1, g1.x, a1.x); a1.y = fmaf(e1, g1.y, a1.y);
            a1.z = fmaf(e1, g1.z, a1.z); a1.w = fmaf(e1, g1.w, a1.w);
        }
        float4 acc = make_float4(a0.x+a1.x, a0.y+a1.y, a0.z+a1.z, a0.w+a1.w);
        __syncthreads();
        ((float4*)red)[ns * 32 + j4] = acc;
        __syncthreads();
        if (tid < 128) {
            float s = 0.f;
            #pragma unroll
            for (int k = 0; k < 8; k++) s += red[k * 128 + tid];
            g_kci[b * 128 + tid] = s;
        }
    } else if (blk < 296) {
        int base = (blk - 288) * 2048;
        for (int i = tid; i < 2048; i += 256)
            g_kcg[base + i] = sigf(kc_gamma[base + i]);
    } else if (blk < 304) {
        // epart[j][d] = fpart_b[d] + sum_k W_kc[k,j] * fpart_w[d, 64+k]
        int jb = blk - 296;                              // 16 j's per block
        for (int i = tid; i < 64 * 64; i += 256) {
            int dd = i >> 6, k = i & 63;
            sbuf[dd * 65 + k] = fpart_w[dd * 128 + 64 + k];
        }
        __syncthreads();
        #pragma unroll
        for (int o = tid; o < 1024; o += 256) {
            int j = jb * 16 + (o >> 6), d = o & 63;
            float acc = fpart_b[d];
            #pragma unroll 8
            for (int k = 0; k < 64; k++)
                acc = fmaf(W_kc[k * 128 + j], sbuf[d * 65 + k], acc);
            g_epart[j * 64 + d] = acc;
        }
    } else {
        // transposes: input-linear (coalesced LDG), scattered STG (no stall)
        int idx0 = (blk - 304) * 3584;
        for (int c = 0; c < 3584; c += 256) {
            int idx = idx0 + c + tid;                    // 0..57343
            if (idx < 12288) {
                int t = idx / 64, k = idx & 63;
                g_twihT[k * 192 + t] = tgru_wih[idx];
            } else if (idx < 24576) {
                int r = idx - 12288; int t = r / 64, k = r & 63;
                g_twhhT[k * 192 + t] = tgru_whh[r];
            } else if (idx < 36864) {
                int r = idx - 24576; int t = r / 64, k = r & 63;
                g_uwihT[k * 192 + t] = ugru_wih[r];
            } else if (idx < 49152) {
                int r = idx - 36864; int t = r / 64, k = r & 63;
                g_uwhhT[k * 192 + t] = ugru_whh[r];
            } else if (idx < 53248) {
                int r = idx - 49152; int d = r >> 6, k = r & 63;
                g_WdhT[k * 64 + d] = fpart_w[d * 128 + k];   // first-half read, row-coalesced
            } else {
                int r = idx - 53248; int d = r >> 6, k = r & 63;
                g_ulinT[k * 64 + d] = ulin_w[r];
            }
        }
    }
}

// ---------------- K2: git + th-GRU + new_h + dpart (16 rows/block) ---------
__global__ void __launch_bounds__(256) k2(
    const float* __restrict__ h, const float* __restrict__ tgru_bih,
    const float* __restrict__ tgru_bhh)
{
    __shared__ float x_s[64];
    __shared__ float git_s[192];
    __shared__ float h_s[16][64];
    __shared__ float delta_s[16][64];

    int tid = threadIdx.x;
    int row0 = blockIdx.x * 16;
    int b = row0 >> 7;

    if (tid < 64) x_s[tid] = g_x[b * 64 + tid];
    ((float4*)h_s)[tid] = ((const float4*)(h + row0 * 64))[tid];
    __syncthreads();

    if (tid < 192) {
        float acc = tgru_bih[tid];
        #pragma unroll 8
        for (int k = 0; k < 64; k++)
            acc = fmaf(x_s[k], g_twihT[k * 192 + tid], acc);
        git_s[tid] = acc;
    }

    int l = tid >> 4, d4 = tid & 15;
    int row = row0 + l;
    const float4* bhh4 = (const float4*)tgru_bhh;
    float4 ar = bhh4[d4], az = bhh4[16 + d4], an = bhh4[32 + d4];
    const float4* whh4 = (const float4*)g_twhhT;
    __syncthreads();

    #pragma unroll 8
    for (int k = 0; k < 64; k++) {
        float hk = h_s[l][k];
        float4 wr = whh4[k * 48 + d4];
        float4 wz = whh4[k * 48 + 16 + d4];
        float4 wn = whh4[k * 48 + 32 + d4];
        ar.x = fmaf(hk, wr.x, ar.x); ar.y = fmaf(hk, wr.y, ar.y);
        ar.z = fmaf(hk, wr.z, ar.z); ar.w = fmaf(hk, wr.w, ar.w);
        az.x = fmaf(hk, wz.x, az.x); az.y = fmaf(hk, wz.y, az.y);
        az.z = fmaf(hk, wz.z, az.z); az.w = fmaf(hk, wz.w, az.w);
        an.x = fmaf(hk, wn.x, an.x); an.y = fmaf(hk, wn.y, an.y);
        an.z = fmaf(hk, wn.z, an.z); an.w = fmaf(hk, wn.w, an.w);
    }

    float kciv = g_kci[row];
    float4 hv  = ((const float4*)h_s[l])[d4];
    float4 gir = ((const float4*)git_s)[d4];
    float4 giz = ((const float4*)git_s)[16 + d4];
    float4 gin = ((const float4*)git_s)[32 + d4];

    float4 nh4, dl4;
    {
        float r0 = sigf(gir.x + ar.x), z0 = sigf(giz.x + az.x);
        float n0 = tanhfast(gin.x + r0 * an.x);
        float th = (1.f - z0) * n0 + z0 * hv.x;
        dl4.x = kciv * (th - hv.x); nh4.x = hv.x + dl4.x;
    }
    {
        float r0 = sigf(gir.y + ar.y), z0 = sigf(giz.y + az.y);
        float n0 = tanhfast(gin.y + r0 * an.y);
        float th = (1.f - z0) * n0 + z0 * hv.y;
        dl4.y = kciv * (th - hv.y); nh4.y = hv.y + dl4.y;
    }
    {
        float r0 = sigf(gir.z + ar.z), z0 = sigf(giz.z + az.z);
        float n0 = tanhfast(gin.z + r0 * an.z);
        float th = (1.f - z0) * n0 + z0 * hv.z;
        dl4.z = kciv * (th - hv.z); nh4.z = hv.z + dl4.z;
    }
    {
        float r0 = sigf(gir.w + ar.w), z0 = sigf(giz.w + az.w);
        float n0 = tanhfast(gin.w + r0 * an.w);
        float th = (1.f - z0) * n0 + z0 * hv.w;
        dl4.w = kciv * (th - hv.w); nh4.w = hv.w + dl4.w;
    }
    ((float4*)(g_newh + row * 64))[d4] = nh4;
    ((float4*)delta_s[l])[d4] = dl4;
    __syncthreads();

    float4 acc = make_float4(0.f, 0.f, 0.f, 0.f);
    const float4* wdh4 = (const float4*)g_WdhT;
    #pragma unroll 8
    for (int k = 0; k < 64; k++) {
        float dv = delta_s[l][k];
        float4 w = wdh4[k * 16 + d4];
        acc.x = fmaf(dv, w.x, acc.x); acc.y = fmaf(dv, w.y, acc.y);
        acc.z = fmaf(dv, w.z, acc.z); acc.w = fmaf(dv, w.w, acc.w);
    }
    ((float4*)(g_dpart + row * 64))[d4] = acc;
}

// ---------------- K3: partj reduce + ulin + u-GRU + output ------------------
__global__ void __launch_bounds__(256) k3(
    const float* __restrict__ ugru_bih, const float* __restrict__ ugru_bhh,
    const float* __restrict__ ulin_b, float* __restrict__ out)
{
    __shared__ __align__(16) float sm[10240];        // 40KB
    float4* dpart4 = (float4*)sm;                    // [128][16] float4
    float*  kcgw   = sm + 8192;                      // [128][16]
    float (*partj_s)[64] = (float(*)[64])sm;         // phase-2 aliases
    float (*outj_s)[64]  = (float(*)[64])(sm + 1024);
    float (*newh_s)[64]  = (float(*)[64])(sm + 2048);

    int jt = blockIdx.x, b = blockIdx.y;
    int tid = threadIdx.x;
    int jl = tid >> 4, d4 = tid & 15;
    int j = jt * 16 + jl;

    const float4* dp4 = (const float4*)(g_dpart + b * (NKC * 64));
    #pragma unroll
    for (int c = 0; c < 8; c++)
        dpart4[c * 256 + tid] = dp4[c * 256 + tid];
    #pragma unroll
    for (int c = 0; c < 8; c++) {
        int idx = c * 256 + tid;
        int ii = idx >> 4, jj = idx & 15;
        kcgw[idx] = g_kcg[ii * 128 + jt * 16 + jj] * g_kci[b * 128 + ii];
    }
    float4 ep = ((const float4*)g_epart)[j * 16 + d4];
    __syncthreads();

    float4 acc = make_float4(0.f, 0.f, 0.f, 0.f);
    float wk = 0.f;
    #pragma unroll 8
    for (int i = 0; i < NKC; i++) {
        float wv = kcgw[i * 16 + jl];
        float4 p = dpart4[i * 16 + d4];
        acc.x = fmaf(fmaxf(p.x + ep.x, 0.f), wv, acc.x);
        acc.y = fmaf(fmaxf(p.y + ep.y, 0.f), wv, acc.y);
        acc.z = fmaf(fmaxf(p.z + ep.z, 0.f), wv, acc.z);
        acc.w = fmaf(fmaxf(p.w + ep.w, 0.f), wv, acc.w);
        wk += wv;
    }
    __syncthreads();

    ((float4*)partj_s[jl])[d4] = acc;
    float4 nh4 = ((const float4*)g_newh)[(b * 128 + j) * 16 + d4];
    ((float4*)newh_s[jl])[d4] = nh4;
    __syncthreads();

    const float4* ul4 = (const float4*)g_ulinT;
    float4 o = ((const float4*)ulin_b)[d4];
    #pragma unroll 8
    for (int k = 0; k < 64; k++) {
        float pv = partj_s[jl][k];
        float4 w = ul4[k * 16 + d4];
        o.x = fmaf(pv, w.x, o.x); o.y = fmaf(pv, w.y, o.y);
        o.z = fmaf(pv, w.z, o.z); o.w = fmaf(pv, w.w, o.w);
    }
    o.x = fmaxf(o.x, 0.f); o.y = fmaxf(o.y, 0.f);
    o.z = fmaxf(o.z, 0.f); o.w = fmaxf(o.w, 0.f);
    ((float4*)outj_s[jl])[d4] = o;
    __syncthreads();

    const float4* bih4 = (const float4*)ugru_bih;
    const float4* bhh4 = (const float4*)ugru_bhh;
    float4 gr = bih4[d4], gz = bih4[16 + d4], gn = bih4[32 + d4];
    float4 hr = bhh4[d4], hz = bhh4[16 + d4], hn = bhh4[32 + d4];
    const float4* wih4 = (const float4*)g_uwihT;
    const float4* whh4 = (const float4*)g_uwhhT;
    #pragma unroll 4
    for (int k = 0; k < 64; k++) {
        float ok = outj_s[jl][k];
        float nk = newh_s[jl][k];
        float4 wr = wih4[k * 48 + d4];
        float4 wz = wih4[k * 48 + 16 + d4];
        float4 wn = wih4[k * 48 + 32 + d4];
        float4 vr = whh4[k * 48 + d4];
        float4 vz = whh4[k * 48 + 16 + d4];
        float4 vn = whh4[k * 48 + 32 + d4];
        gr.x = fmaf(ok, wr.x, gr.x); gr.y = fmaf(ok, wr.y, gr.y);
        gr.z = fmaf(ok, wr.z, gr.z); gr.w = fmaf(ok, wr.w, gr.w);
        gz.x = fmaf(ok, wz.x, gz.x); gz.y = fmaf(ok, wz.y, gz.y);
        gz.z = fmaf(ok, wz.z, gz.z); gz.w = fmaf(ok, wz.w, gz.w);
        gn.x = fmaf(ok, wn.x, gn.x); gn.y = fmaf(ok, wn.y, gn.y);
        gn.z = fmaf(ok, wn.z, gn.z); gn.w = fmaf(ok, wn.w, gn.w);
        hr.x = fmaf(nk, vr.x, hr.x); hr.y = fmaf(nk, vr.y, hr.y);
        hr.z = fmaf(nk, vr.z, hr.z); hr.w = fmaf(nk, vr.w, hr.w);
        hz.x = fmaf(nk, vz.x, hz.x); hz.y = fmaf(nk, vz.y, hz.y);
        hz.z = fmaf(nk, vz.z, hz.z); hz.w = fmaf(nk, vz.w, hz.w);
        hn.x = fmaf(nk, vn.x, hn.x); hn.y = fmaf(nk, vn.y, hn.y);
        hn.z = fmaf(nk, vn.z, hn.z); hn.w = fmaf(nk, vn.w, hn.w);
    }

    float4 res;
    {
        float r0 = sigf(gr.x + hr.x), z0 = sigf(gz.x + hz.x);
        float n0 = tanhfast(gn.x + r0 * hn.x);
        float uh = (1.f - z0) * n0 + z0 * nh4.x;
        res.x = nh4.x + wk * (uh - nh4.x);
    }
    {
        float r0 = sigf(gr.y + hr.y), z0 = sigf(gz.y + hz.y);
        float n0 = tanhfast(gn.y + r0 * hn.y);
        float uh = (1.f - z0) * n0 + z0 * nh4.y;
        res.y = nh4.y + wk * (uh - nh4.y);
    }
    {
        float r0 = sigf(gr.z + hr.z), z0 = sigf(gz.z + hz.z);
        float n0 = tanhfast(gn.z + r0 * hn.z);
        float uh = (1.f - z0) * n0 + z0 * nh4.z;
        res.z = nh4.z + wk * (uh - nh4.z);
    }
    {
        float r0 = sigf(gr.w + hr.w), z0 = sigf(gz.w + hz.w);
        float n0 = tanhfast(gn.w + r0 * hn.w);
        float uh = (1.f - z0) * n0 + z0 * nh4.w;
        res.w = nh4.w + wk * (uh - nh4.w);
    }
    ((float4*)out)[(b * 128 + j) * 16 + d4] = res;
}

// ---------------- launch ----------------------------------------------------
extern "C" void kernel_launch(void* const* d_in, const int* in_sizes, int n_in,
                              void* d_out, int out_size)
{
    const float* h        = (const float*)d_in[0];
    const float* ex       = (const float*)d_in[1];
    const float* su       = (const float*)d_in[2];
    const float* ex_graph = (const float*)d_in[3];
    const float* kc_gamma = (const float*)d_in[4];
    const float* W_ex     = (const float*)d_in[5];
    const float* W_kc     = (const float*)d_in[6];
    const float* tgru_wih = (const float*)d_in[7];
    const float* tgru_whh = (const float*)d_in[8];
    const float* tgru_bih = (const float*)d_in[9];
    const float* tgru_bhh = (const float*)d_in[10];
    const float* fpart_w  = (const float*)d_in[11];
    const float* fpart_b  = (const float*)d_in[12];
    const float* ulin_w   = (const float*)d_in[13];
    const float* ulin_b   = (const float*)d_in[14];
    const float* ugru_wih = (const float*)d_in[15];
    const float* ugru_whh = (const float*)d_in[16];
    const float* ugru_bih = (const float*)d_in[17];
    const float* ugru_bhh = (const float*)d_in[18];
    float* out = (float*)d_out;

    k0<<<320, 256>>>(ex, su, ex_graph, kc_gamma, W_ex, W_kc,
                     tgru_wih, tgru_whh, fpart_w, fpart_b, ulin_w,
                     ugru_wih, ugru_whh);
    k2<<<256, 256>>>(h, tgru_bih, tgru_bhh);
    dim3 g3(8, 32);
    k3<<<g3, 256>>>(ugru_bih, ugru_bhh, ulin_b, out);
}

// round 7
// speedup vs baseline: 2.6408x; 1.4752x over previous
#include <cuda_runtime.h>
#include <cuda_bf16.h>

#define BB   32
#define NEX  1024
#define NKC  128
#define DH   64

// ---------------- scratch (device globals, 16B-aligned) --------------------
__device__ __align__(16) float g_x[BB * 64];
__device__ __align__(16) float g_kci2[2][BB * NKC];   // two n-half partials
__device__ __align__(16) float g_kcg[NKC * NKC];
__device__ __align__(16) float g_epart[NKC * 64];
__device__ __align__(16) float g_newh[BB * NKC * 64];
__device__ __align__(16) float g_dpart[BB * NKC * 64];
__device__ __align__(16) float g_twihT[64 * 192];
__device__ __align__(16) float g_twhhT[64 * 192];
__device__ __align__(16) float g_WdhT[64 * 64];
__device__ __align__(16) float g_ulinT[64 * 64];
__device__ __align__(16) float g_uwihT[64 * 192];
__device__ __align__(16) float g_uwhhT[64 * 192];

__device__ __forceinline__ float sigf(float v)     { return 1.f / (1.f + __expf(-v)); }
__device__ __forceinline__ float tanhfast(float v) { return 2.f / (1.f + __expf(-2.f * v)) - 1.f; }

// ---------------- K0: precompute, 632 blocks x 256 -------------------------
// blocks   0..511 : x      (2 warps per output, 12-load chains)
// blocks 512..575 : kci    (2 blocks per b, 8-deep load batching)
// blocks 576..583 : kcg sigmoid
// blocks 584..615 : epart  (1 output per thread, 8-deep batching)
// blocks 616..631 : weight transposes
__global__ void __launch_bounds__(256, 1) k0(
    const float* __restrict__ ex, const float* __restrict__ su,
    const float* __restrict__ ex_graph, const float* __restrict__ kc_gamma,
    const float* __restrict__ W_ex, const float* __restrict__ W_kc,
    const float* __restrict__ tgru_wih, const float* __restrict__ tgru_whh,
    const float* __restrict__ fpart_w, const float* __restrict__ fpart_b,
    const float* __restrict__ ulin_w,
    const float* __restrict__ ugru_wih, const float* __restrict__ ugru_whh)
{
    __shared__ __align__(16) float sbuf[4288];
    int blk = blockIdx.x, tid = threadIdx.x;

    if (blk < 512) {
        // x[b,e]: 4 outputs/block, 2 warps per output (each half the n-range)
        int w = tid >> 5, lane = tid & 31;
        int oid = blk * 4 + (w >> 1);          // 0..2047
        int half = w & 1;
        int b = oid >> 6, e = oid & 63;
        const float4* W4  = (const float4*)W_ex + e * 512 + half * 128;
        const float4* ex4 = (const float4*)ex + b * 256 + half * 128;
        float4 ev[4], wa[4], wb[4];
        #pragma unroll
        for (int i = 0; i < 4; i++) {
            int idx = i * 32 + lane;
            ev[i] = ex4[idx];
            wa[i] = W4[idx];
            wb[i] = W4[256 + idx];
        }
        float a1 = 0.f, a2 = 0.f;
        #pragma unroll
        for (int i = 0; i < 4; i++) {
            a1 = fmaf(ev[i].x, wa[i].x, fmaf(ev[i].y, wa[i].y, fmaf(ev[i].z, wa[i].z, fmaf(ev[i].w, wa[i].w, a1))));
            a2 = fmaf(ev[i].x, wb[i].x, fmaf(ev[i].y, wb[i].y, fmaf(ev[i].z, wb[i].z, fmaf(ev[i].w, wb[i].w, a2))));
        }
        #pragma unroll
        for (int o = 16; o; o >>= 1) {
            a1 += __shfl_xor_sync(0xffffffffu, a1, o);
            a2 += __shfl_xor_sync(0xffffffffu, a2, o);
        }
        if (lane == 0) { sbuf[w * 2] = a1; sbuf[w * 2 + 1] = a2; }
        __syncthreads();
        if (tid < 4) {
            int o2 = blk * 4 + tid;
            float s1 = sbuf[tid * 4] + sbuf[tid * 4 + 2];
            float s2 = sbuf[tid * 4 + 1] + sbuf[tid * 4 + 3];
            float s = su[o2 >> 6];
            g_x[o2] = s * s1 + (1.f - s) * s2;
        }
    } else if (blk < 576) {
        // kci partials: block handles (b, n-half). thread = (j4 0..31, ns 0..7), 64 n each.
        int idx = blk - 512;
        int b = idx >> 1, nh = idx & 1;
        float4* exs4 = (float4*)sbuf;
        float*  red  = sbuf + 1024;
        exs4[tid] = ((const float4*)ex)[b * 256 + tid];
        __syncthreads();
        int j4 = tid & 31, ns = tid >> 5;
        const float4* eg4 = (const float4*)ex_graph;
        int n0 = nh * 512 + ns * 64;
        float4 a = make_float4(0.f, 0.f, 0.f, 0.f);
        for (int t = 0; t < 64; t += 8) {
            float4 g[8]; float e[8];
            #pragma unroll
            for (int u = 0; u < 8; u++) {
                g[u] = eg4[(n0 + t + u) * 32 + j4];
                e[u] = sbuf[n0 + t + u];
            }
            #pragma unroll
            for (int u = 0; u < 8; u++) {
                a.x = fmaf(e[u], g[u].x, a.x);
                a.y = fmaf(e[u], g[u].y, a.y);
                a.z = fmaf(e[u], g[u].z, a.z);
                a.w = fmaf(e[u], g[u].w, a.w);
            }
        }
        __syncthreads();
        ((float4*)red)[ns * 32 + j4] = a;
        __syncthreads();
        if (tid < 128) {
            float s = 0.f;
            #pragma unroll
            for (int k = 0; k < 8; k++) s += red[k * 128 + tid];
            g_kci2[nh][b * 128 + tid] = s;
        }
    } else if (blk < 584) {
        int base = (blk - 576) * 2048;
        for (int i = tid; i < 2048; i += 256)
            g_kcg[base + i] = sigf(kc_gamma[base + i]);
    } else if (blk < 616) {
        // epart: 1 output per thread (8192 outputs over 32 blocks)
        for (int i = tid; i < 64 * 64; i += 256) {
            int dd = i >> 6, k = i & 63;
            sbuf[dd * 65 + k] = fpart_w[dd * 128 + 64 + k];
        }
        __syncthreads();
        int gid = (blk - 584) * 256 + tid;
        int j = gid >> 6, d = gid & 63;
        float acc = fpart_b[d];
        for (int t = 0; t < 64; t += 8) {
            float wv[8];
            #pragma unroll
            for (int u = 0; u < 8; u++) wv[u] = W_kc[(t + u) * 128 + j];
            #pragma unroll
            for (int u = 0; u < 8; u++) acc = fmaf(wv[u], sbuf[d * 65 + t + u], acc);
        }
        g_epart[gid] = acc;
    } else {
        // transposes: coalesced LDG, scattered STG
        int idx0 = (blk - 616) * 3584;
        for (int c = 0; c < 3584; c += 256) {
            int idx = idx0 + c + tid;
            if (idx < 12288) {
                int t = idx / 64, k = idx & 63;
                g_twihT[k * 192 + t] = tgru_wih[idx];
            } else if (idx < 24576) {
                int r = idx - 12288; int t = r / 64, k = r & 63;
                g_twhhT[k * 192 + t] = tgru_whh[r];
            } else if (idx < 36864) {
                int r = idx - 24576; int t = r / 64, k = r & 63;
                g_uwihT[k * 192 + t] = ugru_wih[r];
            } else if (idx < 49152) {
                int r = idx - 36864; int t = r / 64, k = r & 63;
                g_uwhhT[k * 192 + t] = ugru_whh[r];
            } else if (idx < 53248) {
                int r = idx - 49152; int d = r >> 6, k = r & 63;
                g_WdhT[k * 64 + d] = fpart_w[d * 128 + k];
            } else {
                int r = idx - 53248; int d = r >> 6, k = r & 63;
                g_ulinT[k * 64 + d] = ulin_w[r];
            }
        }
    }
}

// ---------------- K2: git + th-GRU + new_h + dpart (16 rows/block) ---------
__global__ void __launch_bounds__(256, 1) k2(
    const float* __restrict__ h, const float* __restrict__ tgru_bih,
    const float* __restrict__ tgru_bhh)
{
    __shared__ float x_s[64];
    __shared__ float git_s[192];
    __shared__ float h_s[16][64];
    __shared__ float delta_s[16][64];

    int tid = threadIdx.x;
    int row0 = blockIdx.x * 16;
    int b = row0 >> 7;

    if (tid < 64) x_s[tid] = g_x[b * 64 + tid];
    ((float4*)h_s)[tid] = ((const float4*)(h + row0 * 64))[tid];
    __syncthreads();

    if (tid < 192) {
        float acc = tgru_bih[tid];
        #pragma unroll 8
        for (int k = 0; k < 64; k++)
            acc = fmaf(x_s[k], g_twihT[k * 192 + tid], acc);
        git_s[tid] = acc;
    }

    int l = tid >> 4, d4 = tid & 15;
    int row = row0 + l;
    const float4* bhh4 = (const float4*)tgru_bhh;
    float4 ar = bhh4[d4], az = bhh4[16 + d4], an = bhh4[32 + d4];
    const float4* whh4 = (const float4*)g_twhhT;
    __syncthreads();

    #pragma unroll 8
    for (int k = 0; k < 64; k++) {
        float hk = h_s[l][k];
        float4 wr = whh4[k * 48 + d4];
        float4 wz = whh4[k * 48 + 16 + d4];
        float4 wn = whh4[k * 48 + 32 + d4];
        ar.x = fmaf(hk, wr.x, ar.x); ar.y = fmaf(hk, wr.y, ar.y);
        ar.z = fmaf(hk, wr.z, ar.z); ar.w = fmaf(hk, wr.w, ar.w);
        az.x = fmaf(hk, wz.x, az.x); az.y = fmaf(hk, wz.y, az.y);
        az.z = fmaf(hk, wz.z, az.z); az.w = fmaf(hk, wz.w, az.w);
        an.x = fmaf(hk, wn.x, an.x); an.y = fmaf(hk, wn.y, an.y);
        an.z = fmaf(hk, wn.z, an.z); an.w = fmaf(hk, wn.w, an.w);
    }

    float kciv = g_kci2[0][row] + g_kci2[1][row];
    float4 hv  = ((const float4*)h_s[l])[d4];
    float4 gir = ((const float4*)git_s)[d4];
    float4 giz = ((const float4*)git_s)[16 + d4];
    float4 gin = ((const float4*)git_s)[32 + d4];

    float4 nh4, dl4;
    {
        float r0 = sigf(gir.x + ar.x), z0 = sigf(giz.x + az.x);
        float n0 = tanhfast(gin.x + r0 * an.x);
        float th = (1.f - z0) * n0 + z0 * hv.x;
        dl4.x = kciv * (th - hv.x); nh4.x = hv.x + dl4.x;
    }
    {
        float r0 = sigf(gir.y + ar.y), z0 = sigf(giz.y + az.y);
        float n0 = tanhfast(gin.y + r0 * an.y);
        float th = (1.f - z0) * n0 + z0 * hv.y;
        dl4.y = kciv * (th - hv.y); nh4.y = hv.y + dl4.y;
    }
    {
        float r0 = sigf(gir.z + ar.z), z0 = sigf(giz.z + az.z);
        float n0 = tanhfast(gin.z + r0 * an.z);
        float th = (1.f - z0) * n0 + z0 * hv.z;
        dl4.z = kciv * (th - hv.z); nh4.z = hv.z + dl4.z;
    }
    {
        float r0 = sigf(gir.w + ar.w), z0 = sigf(giz.w + az.w);
        float n0 = tanhfast(gin.w + r0 * an.w);
        float th = (1.f - z0) * n0 + z0 * hv.w;
        dl4.w = kciv * (th - hv.w); nh4.w = hv.w + dl4.w;
    }
    ((float4*)(g_newh + row * 64))[d4] = nh4;
    ((float4*)delta_s[l])[d4] = dl4;
    __syncthreads();

    float4 acc = make_float4(0.f, 0.f, 0.f, 0.f);
    const float4* wdh4 = (const float4*)g_WdhT;
    #pragma unroll 8
    for (int k = 0; k < 64; k++) {
        float dv = delta_s[l][k];
        float4 w = wdh4[k * 16 + d4];
        acc.x = fmaf(dv, w.x, acc.x); acc.y = fmaf(dv, w.y, acc.y);
        acc.z = fmaf(dv, w.z, acc.z); acc.w = fmaf(dv, w.w, acc.w);
    }
    ((float4*)(g_dpart + row * 64))[d4] = acc;
}

// ---------------- K3: partj reduce + ulin + u-GRU + output ------------------
// grid (4 jtiles, 32 b), 256 threads = 16 jl x 16 d4.
// Thread owns j0 = jt*32+jl and j1 = j0+16  (2-j register blocking: every
// weight LDG.128 feeds 8 FMAs).
__global__ void __launch_bounds__(256, 1) k3(
    const float* __restrict__ ugru_bih, const float* __restrict__ ugru_bhh,
    const float* __restrict__ ulin_b, float* __restrict__ out)
{
    __shared__ __align__(16) float sm[12288];        // 48KB
    float4* dpart4 = (float4*)sm;                    // [128][16] float4 (32KB)
    float*  kcgw   = sm + 8192;                      // [128][32]        (16KB)
    // phase-2 aliases
    float (*partj_s)[64] = (float(*)[64])sm;         // [32][64]
    float (*outj_s)[64]  = (float(*)[64])(sm + 2048);
    float (*newh_s)[64]  = (float(*)[64])(sm + 4096);

    int jt = blockIdx.x, b = blockIdx.y;
    int tid = threadIdx.x;
    int jl = tid >> 4, d4 = tid & 15;
    int j0 = jt * 32 + jl, j1 = j0 + 16;

    const float4* dp4 = (const float4*)g_dpart + b * 2048;
    #pragma unroll
    for (int c = 0; c < 8; c++)
        dpart4[c * 256 + tid] = dp4[c * 256 + tid];
    #pragma unroll
    for (int c = 0; c < 16; c++) {
        int idx = c * 256 + tid;
        int ii = idx >> 5, jj = idx & 31;
        kcgw[idx] = g_kcg[ii * 128 + jt * 32 + jj]
                  * (g_kci2[0][b * 128 + ii] + g_kci2[1][b * 128 + ii]);
    }
    float4 ep0 = ((const float4*)g_epart)[j0 * 16 + d4];
    float4 ep1 = ((const float4*)g_epart)[j1 * 16 + d4];
    __syncthreads();

    float4 a0 = make_float4(0.f,0.f,0.f,0.f), a1 = make_float4(0.f,0.f,0.f,0.f);
    float wk0 = 0.f, wk1 = 0.f;
    #pragma unroll 4
    for (int i = 0; i < NKC; i++) {
        float4 p = dpart4[i * 16 + d4];
        float w0 = kcgw[i * 32 + jl];
        float w1 = kcgw[i * 32 + jl + 16];
        a0.x = fmaf(fmaxf(p.x + ep0.x, 0.f), w0, a0.x);
        a0.y = fmaf(fmaxf(p.y + ep0.y, 0.f), w0, a0.y);
        a0.z = fmaf(fmaxf(p.z + ep0.z, 0.f), w0, a0.z);
        a0.w = fmaf(fmaxf(p.w + ep0.w, 0.f), w0, a0.w);
        a1.x = fmaf(fmaxf(p.x + ep1.x, 0.f), w1, a1.x);
        a1.y = fmaf(fmaxf(p.y + ep1.y, 0.f), w1, a1.y);
        a1.z = fmaf(fmaxf(p.z + ep1.z, 0.f), w1, a1.z);
        a1.w = fmaf(fmaxf(p.w + ep1.w, 0.f), w1, a1.w);
        wk0 += w0; wk1 += w1;
    }
    __syncthreads();   // phase-1 smem dead

    ((float4*)partj_s[jl])[d4] = a0;
    ((float4*)partj_s[jl + 16])[d4] = a1;
    // stage newh rows for this 32-j tile
    const float4* nhp = (const float4*)g_newh + b * 2048 + jt * 512;
    #pragma unroll
    for (int c = 0; c < 2; c++)
        ((float4*)newh_s)[c * 256 + tid] = nhp[c * 256 + tid];
    __syncthreads();

    // outj = relu(partj @ ulin_w.T + ulin_b)
    const float4* ul4 = (const float4*)g_ulinT;
    float4 o0 = ((const float4*)ulin_b)[d4];
    float4 o1 = o0;
    #pragma unroll 8
    for (int k = 0; k < 64; k++) {
        float p0 = partj_s[jl][k];
        float p1 = partj_s[jl + 16][k];
        float4 w = ul4[k * 16 + d4];
        o0.x = fmaf(p0, w.x, o0.x); o0.y = fmaf(p0, w.y, o0.y);
        o0.z = fmaf(p0, w.z, o0.z); o0.w = fmaf(p0, w.w, o0.w);
        o1.x = fmaf(p1, w.x, o1.x); o1.y = fmaf(p1, w.y, o1.y);
        o1.z = fmaf(p1, w.z, o1.z); o1.w = fmaf(p1, w.w, o1.w);
    }
    o0.x = fmaxf(o0.x, 0.f); o0.y = fmaxf(o0.y, 0.f);
    o0.z = fmaxf(o0.z, 0.f); o0.w = fmaxf(o0.w, 0.f);
    o1.x = fmaxf(o1.x, 0.f); o1.y = fmaxf(o1.y, 0.f);
    o1.z = fmaxf(o1.z, 0.f); o1.w = fmaxf(o1.w, 0.f);
    ((float4*)outj_s[jl])[d4] = o0;
    ((float4*)outj_s[jl + 16])[d4] = o1;
    __syncthreads();

    // u-GRU for both j's
    const float4* bih4 = (const float4*)ugru_bih;
    const float4* bhh4 = (const float4*)ugru_bhh;
    float4 gr0 = bih4[d4], gz0 = bih4[16 + d4], gn0 = bih4[32 + d4];
    float4 hr0 = bhh4[d4], hz0 = bhh4[16 + d4], hn0 = bhh4[32 + d4];
    float4 gr1 = gr0, gz1 = gz0, gn1 = gn0;
    float4 hr1 = hr0, hz1 = hz0, hn1 = hn0;
    const float4* wih4 = (const float4*)g_uwihT;
    const float4* whh4 = (const float4*)g_uwhhT;
    #pragma unroll 4
    for (int k = 0; k < 64; k++) {
        float ok0 = outj_s[jl][k],      ok1 = outj_s[jl + 16][k];
        float nk0 = newh_s[jl][k],      nk1 = newh_s[jl + 16][k];
        float4 wr = wih4[k * 48 + d4];
        float4 wz = wih4[k * 48 + 16 + d4];
        float4 wn = wih4[k * 48 + 32 + d4];
        float4 vr = whh4[k * 48 + d4];
        float4 vz = whh4[k * 48 + 16 + d4];
        float4 vn = whh4[k * 48 + 32 + d4];
        gr0.x = fmaf(ok0, wr.x, gr0.x); gr0.y = fmaf(ok0, wr.y, gr0.y);
        gr0.z = fmaf(ok0, wr.z, gr0.z); gr0.w = fmaf(ok0, wr.w, gr0.w);
        gz0.x = fmaf(ok0, wz.x, gz0.x); gz0.y = fmaf(ok0, wz.y, gz0.y);
        gz0.z = fmaf(ok0, wz.z, gz0.z); gz0.w = fmaf(ok0, wz.w, gz0.w);
        gn0.x = fmaf(ok0, wn.x, gn0.x); gn0.y = fmaf(ok0, wn.y, gn0.y);
        gn0.z = fmaf(ok0, wn.z, gn0.z); gn0.w = fmaf(ok0, wn.w, gn0.w);
        hr0.x = fmaf(nk0, vr.x, hr0.x); hr0.y = fmaf(nk0, vr.y, hr0.y);
        hr0.z = fmaf(nk0, vr.z, hr0.z); hr0.w = fmaf(nk0, vr.w, hr0.w);
        hz0.x = fmaf(nk0, vz.x, hz0.x); hz0.y = fmaf(nk0, vz.y, hz0.y);
        hz0.z = fmaf(nk0, vz.z, hz0.z); hz0.w = fmaf(nk0, vz.w, hz0.w);
        hn0.x = fmaf(nk0, vn.x, hn0.x); hn0.y = fmaf(nk0, vn.y, hn0.y);
        hn0.z = fmaf(nk0, vn.z, hn0.z); hn0.w = fmaf(nk0, vn.w, hn0.w);
        gr1.x = fmaf(ok1, wr.x, gr1.x); gr1.y = fmaf(ok1, wr.y, gr1.y);
        gr1.z = fmaf(ok1, wr.z, gr1.z); gr1.w = fmaf(ok1, wr.w, gr1.w);
        gz1.x = fmaf(ok1, wz.x, gz1.x); gz1.y = fmaf(ok1, wz.y, gz1.y);
        gz1.z = fmaf(ok1, wz.z, gz1.z); gz1.w = fmaf(ok1, wz.w, gz1.w);
        gn1.x = fmaf(ok1, wn.x, gn1.x); gn1.y = fmaf(ok1, wn.y, gn1.y);
        gn1.z = fmaf(ok1, wn.z, gn1.z); gn1.w = fmaf(ok1, wn.w, gn1.w);
        hr1.x = fmaf(nk1, vr.x, hr1.x); hr1.y = fmaf(nk1, vr.y, hr1.y);
        hr1.z = fmaf(nk1, vr.z, hr1.z); hr1.w = fmaf(nk1, vr.w, hr1.w);
        hz1.x = fmaf(nk1, vz.x, hz1.x); hz1.y = fmaf(nk1, vz.y, hz1.y);
        hz1.z = fmaf(nk1, vz.z, hz1.z); hz1.w = fmaf(nk1, vz.w, hz1.w);
        hn1.x = fmaf(nk1, vn.x, hn1.x); hn1.y = fmaf(nk1, vn.y, hn1.y);
        hn1.z = fmaf(nk1, vn.z, hn1.z); hn1.w = fmaf(nk1, vn.w, hn1.w);
    }

    float4 nha = ((const float4*)newh_s[jl])[d4];
    float4 nhb = ((const float4*)newh_s[jl + 16])[d4];
    float4 res0, res1;
    {
        float r = sigf(gr0.x + hr0.x), z = sigf(gz0.x + hz0.x);
        float n = tanhfast(gn0.x + r * hn0.x);
        float uh = (1.f - z) * n + z * nha.x;
        res0.x = nha.x + wk0 * (uh - nha.x);
    }
    {
        float r = sigf(gr0.y + hr0.y), z = sigf(gz0.y + hz0.y);
        float n = tanhfast(gn0.y + r * hn0.y);
        float uh = (1.f - z) * n + z * nha.y;
        res0.y = nha.y + wk0 * (uh - nha.y);
    }
    {
        float r = sigf(gr0.z + hr0.z), z = sigf(gz0.z + hz0.z);
        float n = tanhfast(gn0.z + r * hn0.z);
        float uh = (1.f - z) * n + z * nha.z;
        res0.z = nha.z + wk0 * (uh - nha.z);
    }
    {
        float r = sigf(gr0.w + hr0.w), z = sigf(gz0.w + hz0.w);
        float n = tanhfast(gn0.w + r * hn0.w);
        float uh = (1.f - z) * n + z * nha.w;
        res0.w = nha.w + wk0 * (uh - nha.w);
    }
    {
        float r = sigf(gr1.x + hr1.x), z = sigf(gz1.x + hz1.x);
        float n = tanhfast(gn1.x + r * hn1.x);
        float uh = (1.f - z) * n + z * nhb.x;
        res1.x = nhb.x + wk1 * (uh - nhb.x);
    }
    {
        float r = sigf(gr1.y + hr1.y), z = sigf(gz1.y + hz1.y);
        float n = tanhfast(gn1.y + r * hn1.y);
        float uh = (1.f - z) * n + z * nhb.y;
        res1.y = nhb.y + wk1 * (uh - nhb.y);
    }
    {
        float r = sigf(gr1.z + hr1.z), z = sigf(gz1.z + hz1.z);
        float n = tanhfast(gn1.z + r * hn1.z);
        float uh = (1.f - z) * n + z * nhb.z;
        res1.z = nhb.z + wk1 * (uh - nhb.z);
    }
    {
        float r = sigf(gr1.w + hr1.w), z = sigf(gz1.w + hz1.w);
        float n = tanhfast(gn1.w + r * hn1.w);
        float uh = (1.f - z) * n + z * nhb.w;
        res1.w = nhb.w + wk1 * (uh - nhb.w);
    }
    ((float4*)out)[(b * 128 + j0) * 16 + d4] = res0;
    ((float4*)out)[(b * 128 + j1) * 16 + d4] = res1;
}

// ---------------- launch ----------------------------------------------------
extern "C" void kernel_launch(void* const* d_in, const int* in_sizes, int n_in,
                              void* d_out, int out_size)
{
    const float* h        = (const float*)d_in[0];
    const float* ex       = (const float*)d_in[1];
    const float* su       = (const float*)d_in[2];
    const float* ex_graph = (const float*)d_in[3];
    const float* kc_gamma = (const float*)d_in[4];
    const float* W_ex     = (const float*)d_in[5];
    const float* W_kc     = (const float*)d_in[6];
    const float* tgru_wih = (const float*)d_in[7];
    const float* tgru_whh = (const float*)d_in[8];
    const float* tgru_bih = (const float*)d_in[9];
    const float* tgru_bhh = (const float*)d_in[10];
    const float* fpart_w  = (const float*)d_in[11];
    const float* fpart_b  = (const float*)d_in[12];
    const float* ulin_w   = (const float*)d_in[13];
    const float* ulin_b   = (const float*)d_in[14];
    const float* ugru_wih = (const float*)d_in[15];
    const float* ugru_whh = (const float*)d_in[16];
    const float* ugru_bih = (const float*)d_in[17];
    const float* ugru_bhh = (const float*)d_in[18];
    float* out = (float*)d_out;

    k0<<<632, 256>>>(ex, su, ex_graph, kc_gamma, W_ex, W_kc,
                     tgru_wih, tgru_whh, fpart_w, fpart_b, ulin_w,
                     ugru_wih, ugru_whh);
    k2<<<256, 256>>>(h, tgru_bih, tgru_bhh);
    dim3 g3(4, 32);
    k3<<<g3, 256>>>(ugru_bih, ugru_bhh, ulin_b, out);
}

// round 8
// speedup vs baseline: 2.8614x; 1.0835x over previous
#include <cuda_runtime.h>
#include <cuda_bf16.h>

#define BB   32
#define NEX  1024
#define NKC  128
#define DH   64

// ---------------- scratch (device globals, 16B-aligned) --------------------
__device__ __align__(16) float g_x[BB * 64];
__device__ __align__(16) float g_kci2[2][BB * NKC];   // two n-half partials
__device__ __align__(16) float g_kcg[NKC * NKC];
__device__ __align__(16) float g_epart[NKC * 64];
__device__ __align__(16) float g_newh[BB * NKC * 64];
__device__ __align__(16) float g_dpart[BB * NKC * 64];
__device__ __align__(16) float g_twihT[64 * 192];
__device__ __align__(16) float g_twhhT[64 * 192];
__device__ __align__(16) float g_WdhT[64 * 64];
__device__ __align__(16) float g_ulinT[64 * 64];
__device__ __align__(16) float g_uwihT[64 * 192];
__device__ __align__(16) float g_uwhhT[64 * 192];

__device__ __forceinline__ float sigf(float v)     { return 1.f / (1.f + __expf(-v)); }
__device__ __forceinline__ float tanhfast(float v) { return 2.f / (1.f + __expf(-2.f * v)) - 1.f; }

// ---------------- K0: only what K2 needs, 584 blocks x 256 ------------------
// blocks   0..511 : x      (2 warps per output, 12-load chains)
// blocks 512..575 : kci    (2 blocks per b, 8-deep load batching)
// blocks 576..583 : transposes twihT, twhhT, WdhT (28672 elems)
__global__ void __launch_bounds__(256, 1) k0(
    const float* __restrict__ ex, const float* __restrict__ su,
    const float* __restrict__ ex_graph,
    const float* __restrict__ W_ex,
    const float* __restrict__ tgru_wih, const float* __restrict__ tgru_whh,
    const float* __restrict__ fpart_w)
{
    __shared__ __align__(16) float sbuf[2176];
    int blk = blockIdx.x, tid = threadIdx.x;

    if (blk < 512) {
        // x[b,e]: 4 outputs/block, 2 warps per output (each half the n-range)
        int w = tid >> 5, lane = tid & 31;
        int oid = blk * 4 + (w >> 1);          // 0..2047
        int half = w & 1;
        int b = oid >> 6, e = oid & 63;
        const float4* W4  = (const float4*)W_ex + e * 512 + half * 128;
        const float4* ex4 = (const float4*)ex + b * 256 + half * 128;
        float4 ev[4], wa[4], wb[4];
        #pragma unroll
        for (int i = 0; i < 4; i++) {
            int idx = i * 32 + lane;
            ev[i] = ex4[idx];
            wa[i] = W4[idx];
            wb[i] = W4[256 + idx];
        }
        float a1 = 0.f, a2 = 0.f;
        #pragma unroll
        for (int i = 0; i < 4; i++) {
            a1 = fmaf(ev[i].x, wa[i].x, fmaf(ev[i].y, wa[i].y, fmaf(ev[i].z, wa[i].z, fmaf(ev[i].w, wa[i].w, a1))));
            a2 = fmaf(ev[i].x, wb[i].x, fmaf(ev[i].y, wb[i].y, fmaf(ev[i].z, wb[i].z, fmaf(ev[i].w, wb[i].w, a2))));
        }
        #pragma unroll
        for (int o = 16; o; o >>= 1) {
            a1 += __shfl_xor_sync(0xffffffffu, a1, o);
            a2 += __shfl_xor_sync(0xffffffffu, a2, o);
        }
        if (lane == 0) { sbuf[w * 2] = a1; sbuf[w * 2 + 1] = a2; }
        __syncthreads();
        if (tid < 4) {
            int o2 = blk * 4 + tid;
            float s1 = sbuf[tid * 4] + sbuf[tid * 4 + 2];
            float s2 = sbuf[tid * 4 + 1] + sbuf[tid * 4 + 3];
            float s = su[o2 >> 6];
            g_x[o2] = s * s1 + (1.f - s) * s2;
        }
    } else if (blk < 576) {
        // kci partials: block handles (b, n-half). thread = (j4 0..31, ns 0..7), 64 n each.
        int idx = blk - 512;
        int b = idx >> 1, nh = idx & 1;
        float4* exs4 = (float4*)sbuf;
        float*  red  = sbuf + 1024;
        exs4[tid] = ((const float4*)ex)[b * 256 + tid];
        __syncthreads();
        int j4 = tid & 31, ns = tid >> 5;
        const float4* eg4 = (const float4*)ex_graph;
        int n0 = nh * 512 + ns * 64;
        float4 a = make_float4(0.f, 0.f, 0.f, 0.f);
        for (int t = 0; t < 64; t += 8) {
            float4 g[8]; float e[8];
            #pragma unroll
            for (int u = 0; u < 8; u++) {
                g[u] = eg4[(n0 + t + u) * 32 + j4];
                e[u] = sbuf[n0 + t + u];
            }
            #pragma unroll
            for (int u = 0; u < 8; u++) {
                a.x = fmaf(e[u], g[u].x, a.x);
                a.y = fmaf(e[u], g[u].y, a.y);
                a.z = fmaf(e[u], g[u].z, a.z);
                a.w = fmaf(e[u], g[u].w, a.w);
            }
        }
        __syncthreads();
        ((float4*)red)[ns * 32 + j4] = a;
        __syncthreads();
        if (tid < 128) {
            float s = 0.f;
            #pragma unroll
            for (int k = 0; k < 8; k++) s += red[k * 128 + tid];
            g_kci2[nh][b * 128 + tid] = s;
        }
    } else {
        // transposes for k2: twihT (12288), twhhT (12288), WdhT (4096)
        int idx0 = (blk - 576) * 3584;
        for (int c = 0; c < 3584; c += 256) {
            int idx = idx0 + c + tid;                    // 0..28671
            if (idx < 12288) {
                int t = idx / 64, k = idx & 63;
                g_twihT[k * 192 + t] = tgru_wih[idx];
            } else if (idx < 24576) {
                int r = idx - 12288; int t = r / 64, k = r & 63;
                g_twhhT[k * 192 + t] = tgru_whh[r];
            } else {
                int r = idx - 24576; int d = r >> 6, k = r & 63;
                g_WdhT[k * 64 + d] = fpart_w[d * 128 + k];
            }
        }
    }
}

// ---------------- K2: GRU compute + hidden k3-precompute blocks -------------
// blocks   0..255 : git + th-GRU + new_h + dpart (16 rows/block)
// blocks 256..263 : kcg = sigmoid(kc_gamma)
// blocks 264..295 : epart (1 output/thread)
// blocks 296..303 : transposes uwihT, uwhhT, ulinT (28672 elems)
__global__ void __launch_bounds__(256, 1) k2(
    const float* __restrict__ h, const float* __restrict__ tgru_bih,
    const float* __restrict__ tgru_bhh,
    const float* __restrict__ kc_gamma,
    const float* __restrict__ W_kc,
    const float* __restrict__ fpart_w, const float* __restrict__ fpart_b,
    const float* __restrict__ ulin_w,
    const float* __restrict__ ugru_wih, const float* __restrict__ ugru_whh)
{
    __shared__ __align__(16) float sraw[4160];      // 16.6KB, aliased per role
    int blk = blockIdx.x, tid = threadIdx.x;

    if (blk < 256) {
        float* x_s   = sraw;                        // 64
        float* git_s = sraw + 64;                   // 192
        float (*h_s)[64]     = (float(*)[64])(sraw + 256);   // [16][64]
        float (*delta_s)[64] = (float(*)[64])(sraw + 1280);  // [16][64]

        int row0 = blk * 16;
        int b = row0 >> 7;

        if (tid < 64) x_s[tid] = g_x[b * 64 + tid];
        ((float4*)h_s)[tid] = ((const float4*)(h + row0 * 64))[tid];
        __syncthreads();

        if (tid < 192) {
            float acc = tgru_bih[tid];
            #pragma unroll 8
            for (int k = 0; k < 64; k++)
                acc = fmaf(x_s[k], g_twihT[k * 192 + tid], acc);
            git_s[tid] = acc;
        }

        int l = tid >> 4, d4 = tid & 15;
        int row = row0 + l;
        const float4* bhh4 = (const float4*)tgru_bhh;
        float4 ar = bhh4[d4], az = bhh4[16 + d4], an = bhh4[32 + d4];
        const float4* whh4 = (const float4*)g_twhhT;
        __syncthreads();

        #pragma unroll 8
        for (int k = 0; k < 64; k++) {
            float hk = h_s[l][k];
            float4 wr = whh4[k * 48 + d4];
            float4 wz = whh4[k * 48 + 16 + d4];
            float4 wn = whh4[k * 48 + 32 + d4];
            ar.x = fmaf(hk, wr.x, ar.x); ar.y = fmaf(hk, wr.y, ar.y);
            ar.z = fmaf(hk, wr.z, ar.z); ar.w = fmaf(hk, wr.w, ar.w);
            az.x = fmaf(hk, wz.x, az.x); az.y = fmaf(hk, wz.y, az.y);
            az.z = fmaf(hk, wz.z, az.z); az.w = fmaf(hk, wz.w, az.w);
            an.x = fmaf(hk, wn.x, an.x); an.y = fmaf(hk, wn.y, an.y);
            an.z = fmaf(hk, wn.z, an.z); an.w = fmaf(hk, wn.w, an.w);
        }

        float kciv = g_kci2[0][row] + g_kci2[1][row];
        float4 hv  = ((const float4*)h_s[l])[d4];
        float4 gir = ((const float4*)git_s)[d4];
        float4 giz = ((const float4*)git_s)[16 + d4];
        float4 gin = ((const float4*)git_s)[32 + d4];

        float4 nh4, dl4;
        {
            float r0 = sigf(gir.x + ar.x), z0 = sigf(giz.x + az.x);
            float n0 = tanhfast(gin.x + r0 * an.x);
            float th = (1.f - z0) * n0 + z0 * hv.x;
            dl4.x = kciv * (th - hv.x); nh4.x = hv.x + dl4.x;
        }
        {
            float r0 = sigf(gir.y + ar.y), z0 = sigf(giz.y + az.y);
            float n0 = tanhfast(gin.y + r0 * an.y);
            float th = (1.f - z0) * n0 + z0 * hv.y;
            dl4.y = kciv * (th - hv.y); nh4.y = hv.y + dl4.y;
        }
        {
            float r0 = sigf(gir.z + ar.z), z0 = sigf(giz.z + az.z);
            float n0 = tanhfast(gin.z + r0 * an.z);
            float th = (1.f - z0) * n0 + z0 * hv.z;
            dl4.z = kciv * (th - hv.z); nh4.z = hv.z + dl4.z;
        }
        {
            float r0 = sigf(gir.w + ar.w), z0 = sigf(giz.w + az.w);
            float n0 = tanhfast(gin.w + r0 * an.w);
            float th = (1.f - z0) * n0 + z0 * hv.w;
            dl4.w = kciv * (th - hv.w); nh4.w = hv.w + dl4.w;
        }
        ((float4*)(g_newh + row * 64))[d4] = nh4;
        ((float4*)delta_s[l])[d4] = dl4;
        __syncthreads();

        float4 acc = make_float4(0.f, 0.f, 0.f, 0.f);
        const float4* wdh4 = (const float4*)g_WdhT;
        #pragma unroll 8
        for (int k = 0; k < 64; k++) {
            float dv = delta_s[l][k];
            float4 w = wdh4[k * 16 + d4];
            acc.x = fmaf(dv, w.x, acc.x); acc.y = fmaf(dv, w.y, acc.y);
            acc.z = fmaf(dv, w.z, acc.z); acc.w = fmaf(dv, w.w, acc.w);
        }
        ((float4*)(g_dpart + row * 64))[d4] = acc;
    } else if (blk < 264) {
        int base = (blk - 256) * 2048;
        for (int i = tid; i < 2048; i += 256)
            g_kcg[base + i] = sigf(kc_gamma[base + i]);
    } else if (blk < 296) {
        // epart[j][d] = fpart_b[d] + sum_k W_kc[k,j] * fpart_w[d, 64+k]
        for (int i = tid; i < 64 * 64; i += 256) {
            int dd = i >> 6, k = i & 63;
            sraw[dd * 65 + k] = fpart_w[dd * 128 + 64 + k];
        }
        __syncthreads();
        int gid = (blk - 264) * 256 + tid;
        int j = gid >> 6, d = gid & 63;
        float acc = fpart_b[d];
        for (int t = 0; t < 64; t += 8) {
            float wv[8];
            #pragma unroll
            for (int u = 0; u < 8; u++) wv[u] = W_kc[(t + u) * 128 + j];
            #pragma unroll
            for (int u = 0; u < 8; u++) acc = fmaf(wv[u], sraw[d * 65 + t + u], acc);
        }
        g_epart[gid] = acc;
    } else {
        // transposes for k3: uwihT (12288), uwhhT (12288), ulinT (4096)
        int idx0 = (blk - 296) * 3584;
        for (int c = 0; c < 3584; c += 256) {
            int idx = idx0 + c + tid;                    // 0..28671
            if (idx < 12288) {
                int t = idx / 64, k = idx & 63;
                g_uwihT[k * 192 + t] = ugru_wih[idx];
            } else if (idx < 24576) {
                int r = idx - 12288; int t = r / 64, k = r & 63;
                g_uwhhT[k * 192 + t] = ugru_whh[r];
            } else {
                int r = idx - 24576; int d = r >> 6, k = r & 63;
                g_ulinT[k * 64 + d] = ulin_w[r];
            }
        }
    }
}

// ---------------- K3: partj reduce + ulin + u-GRU + output ------------------
// grid (4 jtiles, 32 b), 256 threads = 16 jl x 16 d4; thread owns j0 and j0+16.
__global__ void __launch_bounds__(256, 1) k3(
    const float* __restrict__ ugru_bih, const float* __restrict__ ugru_bhh,
    const float* __restrict__ ulin_b, float* __restrict__ out)
{
    __shared__ __align__(16) float sm[12288];        // 48KB
    float4* dpart4 = (float4*)sm;                    // [128][16] float4 (32KB)
    float*  kcgw   = sm + 8192;                      // [128][32]        (16KB)
    float (*partj_s)[64] = (float(*)[64])sm;         // phase-2 aliases
    float (*outj_s)[64]  = (float(*)[64])(sm + 2048);
    float (*newh_s)[64]  = (float(*)[64])(sm + 4096);

    int jt = blockIdx.x, b = blockIdx.y;
    int tid = threadIdx.x;
    int jl = tid >> 4, d4 = tid & 15;
    int j0 = jt * 32 + jl, j1 = j0 + 16;

    const float4* dp4 = (const float4*)g_dpart + b * 2048;
    #pragma unroll
    for (int c = 0; c < 8; c++)
        dpart4[c * 256 + tid] = dp4[c * 256 + tid];
    #pragma unroll
    for (int c = 0; c < 16; c++) {
        int idx = c * 256 + tid;
        int ii = idx >> 5, jj = idx & 31;
        kcgw[idx] = g_kcg[ii * 128 + jt * 32 + jj]
                  * (g_kci2[0][b * 128 + ii] + g_kci2[1][b * 128 + ii]);
    }
    float4 ep0 = ((const float4*)g_epart)[j0 * 16 + d4];
    float4 ep1 = ((const float4*)g_epart)[j1 * 16 + d4];
    __syncthreads();

    float4 a0 = make_float4(0.f,0.f,0.f,0.f), a1 = make_float4(0.f,0.f,0.f,0.f);
    float wk0 = 0.f, wk1 = 0.f;
    #pragma unroll 4
    for (int i = 0; i < NKC; i++) {
        float4 p = dpart4[i * 16 + d4];
        float w0 = kcgw[i * 32 + jl];
        float w1 = kcgw[i * 32 + jl + 16];
        a0.x = fmaf(fmaxf(p.x + ep0.x, 0.f), w0, a0.x);
        a0.y = fmaf(fmaxf(p.y + ep0.y, 0.f), w0, a0.y);
        a0.z = fmaf(fmaxf(p.z + ep0.z, 0.f), w0, a0.z);
        a0.w = fmaf(fmaxf(p.w + ep0.w, 0.f), w0, a0.w);
        a1.x = fmaf(fmaxf(p.x + ep1.x, 0.f), w1, a1.x);
        a1.y = fmaf(fmaxf(p.y + ep1.y, 0.f), w1, a1.y);
        a1.z = fmaf(fmaxf(p.z + ep1.z, 0.f), w1, a1.z);
        a1.w = fmaf(fmaxf(p.w + ep1.w, 0.f), w1, a1.w);
        wk0 += w0; wk1 += w1;
    }
    __syncthreads();   // phase-1 smem dead

    ((float4*)partj_s[jl])[d4] = a0;
    ((float4*)partj_s[jl + 16])[d4] = a1;
    const float4* nhp = (const float4*)g_newh + b * 2048 + jt * 512;
    #pragma unroll
    for (int c = 0; c < 2; c++)
        ((float4*)newh_s)[c * 256 + tid] = nhp[c * 256 + tid];
    __syncthreads();

    const float4* ul4 = (const float4*)g_ulinT;
    float4 o0 = ((const float4*)ulin_b)[d4];
    float4 o1 = o0;
    #pragma unroll 8
    for (int k = 0; k < 64; k++) {
        float p0 = partj_s[jl][k];
        float p1 = partj_s[jl + 16][k];
        float4 w = ul4[k * 16 + d4];
        o0.x = fmaf(p0, w.x, o0.x); o0.y = fmaf(p0, w.y, o0.y);
        o0.z = fmaf(p0, w.z, o0.z); o0.w = fmaf(p0, w.w, o0.w);
        o1.x = fmaf(p1, w.x, o1.x); o1.y = fmaf(p1, w.y, o1.y);
        o1.z = fmaf(p1, w.z, o1.z); o1.w = fmaf(p1, w.w, o1.w);
    }
    o0.x = fmaxf(o0.x, 0.f); o0.y = fmaxf(o0.y, 0.f);
    o0.z = fmaxf(o0.z, 0.f); o0.w = fmaxf(o0.w, 0.f);
    o1.x = fmaxf(o1.x, 0.f); o1.y = fmaxf(o1.y, 0.f);
    o1.z = fmaxf(o1.z, 0.f); o1.w = fmaxf(o1.w, 0.f);
    ((float4*)outj_s[jl])[d4] = o0;
    ((float4*)outj_s[jl + 16])[d4] = o1;
    __syncthreads();

    const float4* bih4 = (const float4*)ugru_bih;
    const float4* bhh4 = (const float4*)ugru_bhh;
    float4 gr0 = bih4[d4], gz0 = bih4[16 + d4], gn0 = bih4[32 + d4];
    float4 hr0 = bhh4[d4], hz0 = bhh4[16 + d4], hn0 = bhh4[32 + d4];
    float4 gr1 = gr0, gz1 = gz0, gn1 = gn0;
    float4 hr1 = hr0, hz1 = hz0, hn1 = hn0;
    const float4* wih4 = (const float4*)g_uwihT;
    const float4* whh4 = (const float4*)g_uwhhT;
    #pragma unroll 4
    for (int k = 0; k < 64; k++) {
        float ok0 = outj_s[jl][k],      ok1 = outj_s[jl + 16][k];
        float nk0 = newh_s[jl][k],      nk1 = newh_s[jl + 16][k];
        float4 wr = wih4[k * 48 + d4];
        float4 wz = wih4[k * 48 + 16 + d4];
        float4 wn = wih4[k * 48 + 32 + d4];
        float4 vr = whh4[k * 48 + d4];
        float4 vz = whh4[k * 48 + 16 + d4];
        float4 vn = whh4[k * 48 + 32 + d4];
        gr0.x = fmaf(ok0, wr.x, gr0.x); gr0.y = fmaf(ok0, wr.y, gr0.y);
        gr0.z = fmaf(ok0, wr.z, gr0.z); gr0.w = fmaf(ok0, wr.w, gr0.w);
        gz0.x = fmaf(ok0, wz.x, gz0.x); gz0.y = fmaf(ok0, wz.y, gz0.y);
        gz0.z = fmaf(ok0, wz.z, gz0.z); gz0.w = fmaf(ok0, wz.w, gz0.w);
        gn0.x = fmaf(ok0, wn.x, gn0.x); gn0.y = fmaf(ok0, wn.y, gn0.y);
        gn0.z = fmaf(ok0, wn.z, gn0.z); gn0.w = fmaf(ok0, wn.w, gn0.w);
        hr0.x = fmaf(nk0, vr.x, hr0.x); hr0.y = fmaf(nk0, vr.y, hr0.y);
        hr0.z = fmaf(nk0, vr.z, hr0.z); hr0.w = fmaf(nk0, vr.w, hr0.w);
        hz0.x = fmaf(nk0, vz.x, hz0.x); hz0.y = fmaf(nk0, vz.y, hz0.y);
        hz0.z = fmaf(nk0, vz.z, hz0.z); hz0.w = fmaf(nk0, vz.w, hz0.w);
        hn0.x = fmaf(nk0, vn.x, hn0.x); hn0.y = fmaf(nk0, vn.y, hn0.y);
        hn0.z = fmaf(nk0, vn.z, hn0.z); hn0.w = fmaf(nk0, vn.w, hn0.w);
        gr1.x = fmaf(ok1, wr.x, gr1.x); gr1.y = fmaf(ok1, wr.y, gr1.y);
        gr1.z = fmaf(ok1, wr.z, gr1.z); gr1.w = fmaf(ok1, wr.w, gr1.w);
        gz1.x = fmaf(ok1, wz.x, gz1.x); gz1.y = fmaf(ok1, wz.y, gz1.y);
        gz1.z = fmaf(ok1, wz.z, gz1.z); gz1.w = fmaf(ok1, wz.w, gz1.w);
        gn1.x = fmaf(ok1, wn.x, gn1.x); gn1.y = fmaf(ok1, wn.y, gn1.y);
        gn1.z = fmaf(ok1, wn.z, gn1.z); gn1.w = fmaf(ok1, wn.w, gn1.w);
        hr1.x = fmaf(nk1, vr.x, hr1.x); hr1.y = fmaf(nk1, vr.y, hr1.y);
        hr1.z = fmaf(nk1, vr.z, hr1.z); hr1.w = fmaf(nk1, vr.w, hr1.w);
        hz1.x = fmaf(nk1, vz.x, hz1.x); hz1.y = fmaf(nk1, vz.y, hz1.y);
        hz1.z = fmaf(nk1, vz.z, hz1.z); hz1.w = fmaf(nk1, vz.w, hz1.w);
        hn1.x = fmaf(nk1, vn.x, hn1.x); hn1.y = fmaf(nk1, vn.y, hn1.y);
        hn1.z = fmaf(nk1, vn.z, hn1.z); hn1.w = fmaf(nk1, vn.w, hn1.w);
    }

    float4 nha = ((const float4*)newh_s[jl])[d4];
    float4 nhb = ((const float4*)newh_s[jl + 16])[d4];
    float4 res0, res1;
    {
        float r = sigf(gr0.x + hr0.x), z = sigf(gz0.x + hz0.x);
        float n = tanhfast(gn0.x + r * hn0.x);
        float uh = (1.f - z) * n + z * nha.x;
        res0.x = nha.x + wk0 * (uh - nha.x);
    }
    {
        float r = sigf(gr0.y + hr0.y), z = sigf(gz0.y + hz0.y);
        float n = tanhfast(gn0.y + r * hn0.y);
        float uh = (1.f - z) * n + z * nha.y;
        res0.y = nha.y + wk0 * (uh - nha.y);
    }
    {
        float r = sigf(gr0.z + hr0.z), z = sigf(gz0.z + hz0.z);
        float n = tanhfast(gn0.z + r * hn0.z);
        float uh = (1.f - z) * n + z * nha.z;
        res0.z = nha.z + wk0 * (uh - nha.z);
    }
    {
        float r = sigf(gr0.w + hr0.w), z = sigf(gz0.w + hz0.w);
        float n = tanhfast(gn0.w + r * hn0.w);
        float uh = (1.f - z) * n + z * nha.w;
        res0.w = nha.w + wk0 * (uh - nha.w);
    }
    {
        float r = sigf(gr1.x + hr1.x), z = sigf(gz1.x + hz1.x);
        float n = tanhfast(gn1.x + r * hn1.x);
        float uh = (1.f - z) * n + z * nhb.x;
        res1.x = nhb.x + wk1 * (uh - nhb.x);
    }
    {
        float r = sigf(gr1.y + hr1.y), z = sigf(gz1.y + hz1.y);
        float n = tanhfast(gn1.y + r * hn1.y);
        float uh = (1.f - z) * n + z * nhb.y;
        res1.y = nhb.y + wk1 * (uh - nhb.y);
    }
    {
        float r = sigf(gr1.z + hr1.z), z = sigf(gz1.z + hz1.z);
        float n = tanhfast(gn1.z + r * hn1.z);
        float uh = (1.f - z) * n + z * nhb.z;
        res1.z = nhb.z + wk1 * (uh - nhb.z);
    }
    {
        float r = sigf(gr1.w + hr1.w), z = sigf(gz1.w + hz1.w);
        float n = tanhfast(gn1.w + r * hn1.w);
        float uh = (1.f - z) * n + z * nhb.w;
        res1.w = nhb.w + wk1 * (uh - nhb.w);
    }
    ((float4*)out)[(b * 128 + j0) * 16 + d4] = res0;
    ((float4*)out)[(b * 128 + j1) * 16 + d4] = res1;
}

// ---------------- launch ----------------------------------------------------
extern "C" void kernel_launch(void* const* d_in, const int* in_sizes, int n_in,
                              void* d_out, int out_size)
{
    const float* h        = (const float*)d_in[0];
    const float* ex       = (const float*)d_in[1];
    const float* su       = (const float*)d_in[2];
    const float* ex_graph = (const float*)d_in[3];
    const float* kc_gamma = (const float*)d_in[4];
    const float* W_ex     = (const float*)d_in[5];
    const float* W_kc     = (const float*)d_in[6];
    const float* tgru_wih = (const float*)d_in[7];
    const float* tgru_whh = (const float*)d_in[8];
    const float* tgru_bih = (const float*)d_in[9];
    const float* tgru_bhh = (const float*)d_in[10];
    const float* fpart_w  = (const float*)d_in[11];
    const float* fpart_b  = (const float*)d_in[12];
    const float* ulin_w   = (const float*)d_in[13];
    const float* ulin_b   = (const float*)d_in[14];
    const float* ugru_wih = (const float*)d_in[15];
    const float* ugru_whh = (const float*)d_in[16];
    const float* ugru_bih = (const float*)d_in[17];
    const float* ugru_bhh = (const float*)d_in[18];
    float* out = (float*)d_out;

    k0<<<584, 256>>>(ex, su, ex_graph, W_ex, tgru_wih, tgru_whh, fpart_w);
    k2<<<304, 256>>>(h, tgru_bih, tgru_bhh, kc_gamma, W_kc,
                     fpart_w, fpart_b, ulin_w, ugru_wih, ugru_whh);
    dim3 g3(4, 32);
    k3<<<g3, 256>>>(ugru_bih, ugru_bhh, ulin_b, out);
}

// round 10
// speedup vs baseline: 3.0930x; 1.0809x over previous
#include <cuda_runtime.h>
#include <cuda_bf16.h>

#define BB   32
#define NEX  1024
#define NKC  128
#define DH   64

typedef unsigned long long u64;

// ---------------- scratch (device globals, 16B-aligned) --------------------
__device__ __align__(16) float g_x[BB * 64];
__device__ __align__(16) float g_kci2[2][BB * NKC];   // two n-half partials
__device__ __align__(16) float g_kcg[NKC * NKC];
__device__ __align__(16) float g_epart[NKC * 64];
__device__ __align__(16) float g_newh[BB * NKC * 64];
__device__ __align__(16) float g_dpart[BB * NKC * 64];
__device__ __align__(16) float g_twhhT[64 * 192];
__device__ __align__(16) float g_WdhT[64 * 64];
__device__ __align__(16) float g_ulinT[64 * 64];
__device__ __align__(16) float g_uwihT[64 * 192];
__device__ __align__(16) float g_uwhhT[64 * 192];

__device__ __forceinline__ float sigf(float v)     { return 1.f / (1.f + __expf(-v)); }
__device__ __forceinline__ float tanhfast(float v) { return 2.f / (1.f + __expf(-2.f * v)) - 1.f; }

// packed f32x2 helpers (FFMA2: 2 fp32 lanes per issue slot)
__device__ __forceinline__ u64 pack2(float x, float y) {
    u64 r; asm("mov.b64 %0, {%1, %2};" : "=l"(r) : "f"(x), "f"(y)); return r;
}
__device__ __forceinline__ void fma2(u64& acc, u64 a, u64 b) {
    asm("fma.rn.f32x2 %0, %1, %2, %0;" : "+l"(acc) : "l"(a), "l"(b));
}
__device__ __forceinline__ void unpack2(u64 v, float& x, float& y) {
    asm("mov.b64 {%0, %1}, %2;" : "=f"(x), "=f"(y) : "l"(v));
}

// ---------------- K0: only what K2 needs, 584 blocks x 256 ------------------
// blocks   0..511 : x      (2 warps per output, 12-load chains)
// blocks 512..575 : kci    (2 blocks per b, 8-deep load batching)
// blocks 576..583 : transposes twhhT, WdhT (16384 elems)
__global__ void __launch_bounds__(256, 1) k0(
    const float* __restrict__ ex, const float* __restrict__ su,
    const float* __restrict__ ex_graph,
    const float* __restrict__ W_ex,
    const float* __restrict__ tgru_whh,
    const float* __restrict__ fpart_w)
{
    __shared__ __align__(16) float sbuf[2176];
    int blk = blockIdx.x, tid = threadIdx.x;

    if (blk < 512) {
        int w = tid >> 5, lane = tid & 31;
        int oid = blk * 4 + (w >> 1);          // 0..2047
        int half = w & 1;
        int b = oid >> 6, e = oid & 63;
        const float4* W4  = (const float4*)W_ex + e * 512 + half * 128;
        const float4* ex4 = (const float4*)ex + b * 256 + half * 128;
        float4 ev[4], wa[4], wb[4];
        #pragma unroll
        for (int i = 0; i < 4; i++) {
            int idx = i * 32 + lane;
            ev[i] = ex4[idx];
            wa[i] = W4[idx];
            wb[i] = W4[256 + idx];
        }
        float a1 = 0.f, a2 = 0.f;
        #pragma unroll
        for (int i = 0; i < 4; i++) {
            a1 = fmaf(ev[i].x, wa[i].x, fmaf(ev[i].y, wa[i].y, fmaf(ev[i].z, wa[i].z, fmaf(ev[i].w, wa[i].w, a1))));
            a2 = fmaf(ev[i].x, wb[i].x, fmaf(ev[i].y, wb[i].y, fmaf(ev[i].z, wb[i].z, fmaf(ev[i].w, wb[i].w, a2))));
        }
        #pragma unroll
        for (int o = 16; o; o >>= 1) {
            a1 += __shfl_xor_sync(0xffffffffu, a1, o);
            a2 += __shfl_xor_sync(0xffffffffu, a2, o);
        }
        if (lane == 0) { sbuf[w * 2] = a1; sbuf[w * 2 + 1] = a2; }
        __syncthreads();
        if (tid < 4) {
            int o2 = blk * 4 + tid;
            float s1 = sbuf[tid * 4] + sbuf[tid * 4 + 2];
            float s2 = sbuf[tid * 4 + 1] + sbuf[tid * 4 + 3];
            float s = su[o2 >> 6];
            g_x[o2] = s * s1 + (1.f - s) * s2;
        }
    } else if (blk < 576) {
        int idx = blk - 512;
        int b = idx >> 1, nh = idx & 1;
        float4* exs4 = (float4*)sbuf;
        float*  red  = sbuf + 1024;
        exs4[tid] = ((const float4*)ex)[b * 256 + tid];
        __syncthreads();
        int j4 = tid & 31, ns = tid >> 5;
        const float4* eg4 = (const float4*)ex_graph;
        int n0 = nh * 512 + ns * 64;
        float4 a = make_float4(0.f, 0.f, 0.f, 0.f);
        for (int t = 0; t < 64; t += 8) {
            float4 g[8]; float e[8];
            #pragma unroll
            for (int u = 0; u < 8; u++) {
                g[u] = eg4[(n0 + t + u) * 32 + j4];
                e[u] = sbuf[n0 + t + u];
            }
            #pragma unroll
            for (int u = 0; u < 8; u++) {
                a.x = fmaf(e[u], g[u].x, a.x);
                a.y = fmaf(e[u], g[u].y, a.y);
                a.z = fmaf(e[u], g[u].z, a.z);
                a.w = fmaf(e[u], g[u].w, a.w);
            }
        }
        __syncthreads();
        ((float4*)red)[ns * 32 + j4] = a;
        __syncthreads();
        if (tid < 128) {
            float s = 0.f;
            #pragma unroll
            for (int k = 0; k < 8; k++) s += red[k * 128 + tid];
            g_kci2[nh][b * 128 + tid] = s;
        }
    } else {
        // transposes for k2: twhhT (12288), WdhT (4096)
        int idx0 = (blk - 576) * 2048;
        for (int c = 0; c < 2048; c += 256) {
            int idx = idx0 + c + tid;                    // 0..16383
            if (idx < 12288) {
                int t = idx / 64, k = idx & 63;
                g_twhhT[k * 192 + t] = tgru_whh[idx];
            } else {
                int r = idx - 12288; int d = r >> 6, k = r & 63;
                g_WdhT[k * 64 + d] = fpart_w[d * 128 + k];
            }
        }
    }
}

// ---------------- K2: GRU compute + hidden k3-precompute blocks -------------
// blocks   0..255 : git + th-GRU + new_h + dpart (16 rows/block)
// blocks 256..263 : kcg = sigmoid(kc_gamma)
// blocks 264..295 : epart (1 output/thread)
// blocks 296..303 : transposes uwihT, uwhhT, ulinT
__global__ void __launch_bounds__(256, 1) k2(
    const float* __restrict__ h,
    const float* __restrict__ tgru_wih,
    const float* __restrict__ tgru_bih,
    const float* __restrict__ tgru_bhh,
    const float* __restrict__ kc_gamma,
    const float* __restrict__ W_kc,
    const float* __restrict__ fpart_w, const float* __restrict__ fpart_b,
    const float* __restrict__ ulin_w,
    const float* __restrict__ ugru_wih, const float* __restrict__ ugru_whh)
{
    __shared__ __align__(16) float sraw[4160];
    int blk = blockIdx.x, tid = threadIdx.x;

    if (blk < 256) {
        float* x_s   = sraw;                        // 64
        float* git_s = sraw + 64;                   // 192
        float (*h_s)[64]     = (float(*)[64])(sraw + 256);
        float (*delta_s)[64] = (float(*)[64])(sraw + 1280);

        int row0 = blk * 16;
        int b = row0 >> 7;

        if (tid < 64) x_s[tid] = g_x[b * 64 + tid];
        ((float4*)h_s)[tid] = ((const float4*)(h + row0 * 64))[tid];
        __syncthreads();

        if (tid < 192) {
            // git[t] = bih[t] + dot(x, wih_row_t)   (row-major, 16 hoisted LDG.128)
            const ulonglong2* wrow = (const ulonglong2*)(tgru_wih + tid * 64);
            const ulonglong2* xs2  = (const ulonglong2*)x_s;
            u64 a0 = 0ull, a1 = 0ull;
            #pragma unroll
            for (int i = 0; i < 16; i++) {
                ulonglong2 w = wrow[i];
                ulonglong2 xv = xs2[i];
                fma2(a0, w.x, xv.x);
                fma2(a1, w.y, xv.y);
            }
            float f0, f1, f2, f3;
            unpack2(a0, f0, f1); unpack2(a1, f2, f3);
            git_s[tid] = tgru_bih[tid] + ((f0 + f1) + (f2 + f3));
        }

        int l = tid >> 4, d4 = tid & 15;
        int row = row0 + l;
        // packed gate accumulators, initialized from bhh bias pairs
        ulonglong2 arp = ((const ulonglong2*)tgru_bhh)[d4];
        ulonglong2 azp = ((const ulonglong2*)tgru_bhh)[16 + d4];
        ulonglong2 anp = ((const ulonglong2*)tgru_bhh)[32 + d4];
        const ulonglong2* whh2 = (const ulonglong2*)g_twhhT;
        __syncthreads();

        #pragma unroll 8
        for (int k = 0; k < 64; k++) {
            float hk = h_s[l][k];
            u64 hp = pack2(hk, hk);
            ulonglong2 wr = whh2[k * 48 + d4];
            ulonglong2 wz = whh2[k * 48 + 16 + d4];
            ulonglong2 wn = whh2[k * 48 + 32 + d4];
            fma2(arp.x, wr.x, hp); fma2(arp.y, wr.y, hp);
            fma2(azp.x, wz.x, hp); fma2(azp.y, wz.y, hp);
            fma2(anp.x, wn.x, hp); fma2(anp.y, wn.y, hp);
        }
        float4 ar, az, an;
        unpack2(arp.x, ar.x, ar.y); unpack2(arp.y, ar.z, ar.w);
        unpack2(azp.x, az.x, az.y); unpack2(azp.y, az.z, az.w);
        unpack2(anp.x, an.x, an.y); unpack2(anp.y, an.z, an.w);

        float kciv = g_kci2[0][row] + g_kci2[1][row];
        float4 hv  = ((const float4*)h_s[l])[d4];
        float4 gir = ((const float4*)git_s)[d4];
        float4 giz = ((const float4*)git_s)[16 + d4];
        float4 gin = ((const float4*)git_s)[32 + d4];

        float4 nh4, dl4;
        {
            float r0 = sigf(gir.x + ar.x), z0 = sigf(giz.x + az.x);
            float n0 = tanhfast(gin.x + r0 * an.x);
            float th = (1.f - z0) * n0 + z0 * hv.x;
            dl4.x = kciv * (th - hv.x); nh4.x = hv.x + dl4.x;
        }
        {
            float r0 = sigf(gir.y + ar.y), z0 = sigf(giz.y + az.y);
            float n0 = tanhfast(gin.y + r0 * an.y);
            float th = (1.f - z0) * n0 + z0 * hv.y;
            dl4.y = kciv * (th - hv.y); nh4.y = hv.y + dl4.y;
        }
        {
            float r0 = sigf(gir.z + ar.z), z0 = sigf(giz.z + az.z);
            float n0 = tanhfast(gin.z + r0 * an.z);
            float th = (1.f - z0) * n0 + z0 * hv.z;
            dl4.z = kciv * (th - hv.z); nh4.z = hv.z + dl4.z;
        }
        {
            float r0 = sigf(gir.w + ar.w), z0 = sigf(giz.w + az.w);
            float n0 = tanhfast(gin.w + r0 * an.w);
            float th = (1.f - z0) * n0 + z0 * hv.w;
            dl4.w = kciv * (th - hv.w); nh4.w = hv.w + dl4.w;
        }
        ((float4*)(g_newh + row * 64))[d4] = nh4;
        ((float4*)delta_s[l])[d4] = dl4;
        __syncthreads();

        u64 ac01 = 0ull, ac23 = 0ull;
        const ulonglong2* wdh2 = (const ulonglong2*)g_WdhT;
        #pragma unroll 8
        for (int k = 0; k < 64; k++) {
            float dv = delta_s[l][k];
            u64 dp = pack2(dv, dv);
            ulonglong2 w = wdh2[k * 16 + d4];
            fma2(ac01, w.x, dp);
            fma2(ac23, w.y, dp);
        }
        float4 acc;
        unpack2(ac01, acc.x, acc.y); unpack2(ac23, acc.z, acc.w);
        ((float4*)(g_dpart + row * 64))[d4] = acc;
    } else if (blk < 264) {
        int base = (blk - 256) * 2048;
        for (int i = tid; i < 2048; i += 256)
            g_kcg[base + i] = sigf(kc_gamma[base + i]);
    } else if (blk < 296) {
        for (int i = tid; i < 64 * 64; i += 256) {
            int dd = i >> 6, k = i & 63;
            sraw[dd * 65 + k] = fpart_w[dd * 128 + 64 + k];
        }
        __syncthreads();
        int gid = (blk - 264) * 256 + tid;
        int j = gid >> 6, d = gid & 63;
        float acc = fpart_b[d];
        for (int t = 0; t < 64; t += 8) {
            float wv[8];
            #pragma unroll
            for (int u = 0; u < 8; u++) wv[u] = W_kc[(t + u) * 128 + j];
            #pragma unroll
            for (int u = 0; u < 8; u++) acc = fmaf(wv[u], sraw[d * 65 + t + u], acc);
        }
        g_epart[gid] = acc;
    } else {
        int idx0 = (blk - 296) * 3584;
        for (int c = 0; c < 3584; c += 256) {
            int idx = idx0 + c + tid;                    // 0..28671
            if (idx < 12288) {
                int t = idx / 64, k = idx & 63;
                g_uwihT[k * 192 + t] = ugru_wih[idx];
            } else if (idx < 24576) {
                int r = idx - 12288; int t = r / 64, k = r & 63;
                g_uwhhT[k * 192 + t] = ugru_whh[r];
            } else {
                int r = idx - 24576; int d = r >> 6, k = r & 63;
                g_ulinT[k * 64 + d] = ulin_w[r];
            }
        }
    }
}

// ---------------- K3: partj reduce + ulin + u-GRU + output ------------------
// grid (4 jtiles, 32 b), 256 threads = 16 jl x 16 d4; thread owns j0 and j0+16.
__global__ void __launch_bounds__(256, 1) k3(
    const float* __restrict__ ugru_bih, const float* __restrict__ ugru_bhh,
    const float* __restrict__ ulin_b, float* __restrict__ out)
{
    __shared__ __align__(16) float sm[12288];        // 48KB
    float4* dpart4 = (float4*)sm;                    // [128][16] float4 (32KB)
    float*  kcgw   = sm + 8192;                      // [128][32]        (16KB)
    float (*partj_s)[64] = (float(*)[64])sm;         // phase-2 aliases
    float (*outj_s)[64]  = (float(*)[64])(sm + 2048);
    float (*newh_s)[64]  = (float(*)[64])(sm + 4096);

    int jt = blockIdx.x, b = blockIdx.y;
    int tid = threadIdx.x;
    int jl = tid >> 4, d4 = tid & 15;
    int j0 = jt * 32 + jl, j1 = j0 + 16;

    const float4* dp4 = (const float4*)g_dpart + b * 2048;
    #pragma unroll
    for (int c = 0; c < 8; c++)
        dpart4[c * 256 + tid] = dp4[c * 256 + tid];
    #pragma unroll
    for (int c = 0; c < 16; c++) {
        int idx = c * 256 + tid;
        int ii = idx >> 5, jj = idx & 31;
        kcgw[idx] = g_kcg[ii * 128 + jt * 32 + jj]
                  * (g_kci2[0][b * 128 + ii] + g_kci2[1][b * 128 + ii]);
    }
    float4 ep0 = ((const float4*)g_epart)[j0 * 16 + d4];
    float4 ep1 = ((const float4*)g_epart)[j1 * 16 + d4];
    __syncthreads();

    float4 a0 = make_float4(0.f,0.f,0.f,0.f), a1 = make_float4(0.f,0.f,0.f,0.f);
    float wk0 = 0.f, wk1 = 0.f;
    #pragma unroll 4
    for (int i = 0; i < NKC; i++) {
        float4 p = dpart4[i * 16 + d4];
        float w0 = kcgw[i * 32 + jl];
        float w1 = kcgw[i * 32 + jl + 16];
        a0.x = fmaf(fmaxf(p.x + ep0.x, 0.f), w0, a0.x);
        a0.y = fmaf(fmaxf(p.y + ep0.y, 0.f), w0, a0.y);
        a0.z = fmaf(fmaxf(p.z + ep0.z, 0.f), w0, a0.z);
        a0.w = fmaf(fmaxf(p.w + ep0.w, 0.f), w0, a0.w);
        a1.x = fmaf(fmaxf(p.x + ep1.x, 0.f), w1, a1.x);
        a1.y = fmaf(fmaxf(p.y + ep1.y, 0.f), w1, a1.y);
        a1.z = fmaf(fmaxf(p.z + ep1.z, 0.f), w1, a1.z);
        a1.w = fmaf(fmaxf(p.w + ep1.w, 0.f), w1, a1.w);
        wk0 += w0; wk1 += w1;
    }
    __syncthreads();   // phase-1 smem dead

    ((float4*)partj_s[jl])[d4] = a0;
    ((float4*)partj_s[jl + 16])[d4] = a1;
    const float4* nhp = (const float4*)g_newh + b * 2048 + jt * 512;
    #pragma unroll
    for (int c = 0; c < 2; c++)
        ((float4*)newh_s)[c * 256 + tid] = nhp[c * 256 + tid];
    __syncthreads();

    // outj = relu(partj @ ulin_w.T + ulin_b)   (packed f32x2)
    {
        ulonglong2 ob = ((const ulonglong2*)ulin_b)[d4];
        ulonglong2 o0p = ob, o1p = ob;
        const ulonglong2* ul2 = (const ulonglong2*)g_ulinT;
        #pragma unroll 8
        for (int k = 0; k < 64; k++) {
            float p0 = partj_s[jl][k];
            float p1 = partj_s[jl + 16][k];
            u64 q0 = pack2(p0, p0);
            u64 q1 = pack2(p1, p1);
            ulonglong2 w = ul2[k * 16 + d4];
            fma2(o0p.x, w.x, q0); fma2(o0p.y, w.y, q0);
            fma2(o1p.x, w.x, q1); fma2(o1p.y, w.y, q1);
        }
        float4 o0, o1;
        unpack2(o0p.x, o0.x, o0.y); unpack2(o0p.y, o0.z, o0.w);
        unpack2(o1p.x, o1.x, o1.y); unpack2(o1p.y, o1.z, o1.w);
        o0.x = fmaxf(o0.x, 0.f); o0.y = fmaxf(o0.y, 0.f);
        o0.z = fmaxf(o0.z, 0.f); o0.w = fmaxf(o0.w, 0.f);
        o1.x = fmaxf(o1.x, 0.f); o1.y = fmaxf(o1.y, 0.f);
        o1.z = fmaxf(o1.z, 0.f); o1.w = fmaxf(o1.w, 0.f);
        ((float4*)outj_s[jl])[d4] = o0;
        ((float4*)outj_s[jl + 16])[d4] = o1;
    }
    __syncthreads();

    // u-GRU (packed f32x2: 24 FFMA2/k instead of 48 FFMA)
    ulonglong2 bihr = ((const ulonglong2*)ugru_bih)[d4];
    ulonglong2 bihz = ((const ulonglong2*)ugru_bih)[16 + d4];
    ulonglong2 bihn = ((const ulonglong2*)ugru_bih)[32 + d4];
    ulonglong2 bhhr = ((const ulonglong2*)ugru_bhh)[d4];
    ulonglong2 bhhz = ((const ulonglong2*)ugru_bhh)[16 + d4];
    ulonglong2 bhhn = ((const ulonglong2*)ugru_bhh)[32 + d4];
    ulonglong2 gr0p = bihr, gz0p = bihz, gn0p = bihn;
    ulonglong2 hr0p = bhhr, hz0p = bhhz, hn0p = bhhn;
    ulonglong2 gr1p = bihr, gz1p = bihz, gn1p = bihn;
    ulonglong2 hr1p = bhhr, hz1p = bhhz, hn1p = bhhn;
    const ulonglong2* wih2 = (const ulonglong2*)g_uwihT;
    const ulonglong2* whh2 = (const ulonglong2*)g_uwhhT;
    #pragma unroll 4
    for (int k = 0; k < 64; k++) {
        float ok0 = outj_s[jl][k],      ok1 = outj_s[jl + 16][k];
        float nk0 = newh_s[jl][k],      nk1 = newh_s[jl + 16][k];
        u64 O0 = pack2(ok0, ok0), O1 = pack2(ok1, ok1);
        u64 N0 = pack2(nk0, nk0), N1 = pack2(nk1, nk1);
        ulonglong2 wr = wih2[k * 48 + d4];
        ulonglong2 wz = wih2[k * 48 + 16 + d4];
        ulonglong2 wn = wih2[k * 48 + 32 + d4];
        ulonglong2 vr = whh2[k * 48 + d4];
        ulonglong2 vz = whh2[k * 48 + 16 + d4];
        ulonglong2 vn = whh2[k * 48 + 32 + d4];
        fma2(gr0p.x, wr.x, O0); fma2(gr0p.y, wr.y, O0);
        fma2(gz0p.x, wz.x, O0); fma2(gz0p.y, wz.y, O0);
        fma2(gn0p.x, wn.x, O0); fma2(gn0p.y, wn.y, O0);
        fma2(hr0p.x, vr.x, N0); fma2(hr0p.y, vr.y, N0);
        fma2(hz0p.x, vz.x, N0); fma2(hz0p.y, vz.y, N0);
        fma2(hn0p.x, vn.x, N0); fma2(hn0p.y, vn.y, N0);
        fma2(gr1p.x, wr.x, O1); fma2(gr1p.y, wr.y, O1);
        fma2(gz1p.x, wz.x, O1); fma2(gz1p.y, wz.y, O1);
        fma2(gn1p.x, wn.x, O1); fma2(gn1p.y, wn.y, O1);
        fma2(hr1p.x, vr.x, N1); fma2(hr1p.y, vr.y, N1);
        fma2(hz1p.x, vz.x, N1); fma2(hz1p.y, vz.y, N1);
        fma2(hn1p.x, vn.x, N1); fma2(hn1p.y, vn.y, N1);
    }
    float4 gr0, gz0, gn0, hr0, hz0, hn0, gr1, gz1, gn1, hr1, hz1, hn1;
    unpack2(gr0p.x, gr0.x, gr0.y); unpack2(gr0p.y, gr0.z, gr0.w);
    unpack2(gz0p.x, gz0.x, gz0.y); unpack2(gz0p.y, gz0.z, gz0.w);
    unpack2(gn0p.x, gn0.x, gn0.y); unpack2(gn0p.y, gn0.z, gn0.w);
    unpack2(hr0p.x, hr0.x, hr0.y); unpack2(hr0p.y, hr0.z, hr0.w);
    unpack2(hz0p.x, hz0.x, hz0.y); unpack2(hz0p.y, hz0.z, hz0.w);
    unpack2(hn0p.x, hn0.x, hn0.y); unpack2(hn0p.y, hn0.z, hn0.w);
    unpack2(gr1p.x, gr1.x, gr1.y); unpack2(gr1p.y, gr1.z, gr1.w);
    unpack2(gz1p.x, gz1.x, gz1.y); unpack2(gz1p.y, gz1.z, gz1.w);
    unpack2(gn1p.x, gn1.x, gn1.y); unpack2(gn1p.y, gn1.z, gn1.w);
    unpack2(hr1p.x, hr1.x, hr1.y); unpack2(hr1p.y, hr1.z, hr1.w);
    unpack2(hz1p.x, hz1.x, hz1.y); unpack2(hz1p.y, hz1.z, hz1.w);
    unpack2(hn1p.x, hn1.x, hn1.y); unpack2(hn1p.y, hn1.z, hn1.w);

    float4 nha = ((const float4*)newh_s[jl])[d4];
    float4 nhb = ((const float4*)newh_s[jl + 16])[d4];
    float4 res0, res1;
    {
        float r = sigf(gr0.x + hr0.x), z = sigf(gz0.x + hz0.x);
        float n = tanhfast(gn0.x + r * hn0.x);
        float uh = (1.f - z) * n + z * nha.x;
        res0.x = nha.x + wk0 * (uh - nha.x);
    }
    {
        float r = sigf(gr0.y + hr0.y), z = sigf(gz0.y + hz0.y);
        float n = tanhfast(gn0.y + r * hn0.y);
        float uh = (1.f - z) * n + z * nha.y;
        res0.y = nha.y + wk0 * (uh - nha.y);
    }
    {
        float r = sigf(gr0.z + hr0.z), z = sigf(gz0.z + hz0.z);
        float n = tanhfast(gn0.z + r * hn0.z);
        float uh = (1.f - z) * n + z * nha.z;
        res0.z = nha.z + wk0 * (uh - nha.z);
    }
    {
        float r = sigf(gr0.w + hr0.w), z = sigf(gz0.w + hz0.w);
        float n = tanhfast(gn0.w + r * hn0.w);
        float uh = (1.f - z) * n + z * nha.w;
        res0.w = nha.w + wk0 * (uh - nha.w);
    }
    {
        float r = sigf(gr1.x + hr1.x), z = sigf(gz1.x + hz1.x);
        float n = tanhfast(gn1.x + r * hn1.x);
        float uh = (1.f - z) * n + z * nhb.x;
        res1.x = nhb.x + wk1 * (uh - nhb.x);
    }
    {
        float r = sigf(gr1.y + hr1.y), z = sigf(gz1.y + hz1.y);
        float n = tanhfast(gn1.y + r * hn1.y);
        float uh = (1.f - z) * n + z * nhb.y;
        res1.y = nhb.y + wk1 * (uh - nhb.y);
    }
    {
        float r = sigf(gr1.z + hr1.z), z = sigf(gz1.z + hz1.z);
        float n = tanhfast(gn1.z + r * hn1.z);
        float uh = (1.f - z) * n + z * nhb.z;
        res1.z = nhb.z + wk1 * (uh - nhb.z);
    }
    {
        float r = sigf(gr1.w + hr1.w), z = sigf(gz1.w + hz1.w);
        float n = tanhfast(gn1.w + r * hn1.w);
        float uh = (1.f - z) * n + z * nhb.w;
        res1.w = nhb.w + wk1 * (uh - nhb.w);
    }
    ((float4*)out)[(b * 128 + j0) * 16 + d4] = res0;
    ((float4*)out)[(b * 128 + j1) * 16 + d4] = res1;
}

// ---------------- launch ----------------------------------------------------
extern "C" void kernel_launch(void* const* d_in, const int* in_sizes, int n_in,
                              void* d_out, int out_size)
{
    const float* h        = (const float*)d_in[0];
    const float* ex       = (const float*)d_in[1];
    const float* su       = (const float*)d_in[2];
    const float* ex_graph = (const float*)d_in[3];
    const float* kc_gamma = (const float*)d_in[4];
    const float* W_ex     = (const float*)d_in[5];
    const float* W_kc     = (const float*)d_in[6];
    const float* tgru_wih = (const float*)d_in[7];
    const float* tgru_whh = (const float*)d_in[8];
    const float* tgru_bih = (const float*)d_in[9];
    const float* tgru_bhh = (const float*)d_in[10];
    const float* fpart_w  = (const float*)d_in[11];
    const float* fpart_b  = (const float*)d_in[12];
    const float* ulin_w   = (const float*)d_in[13];
    const float* ulin_b   = (const float*)d_in[14];
    const float* ugru_wih = (const float*)d_in[15];
    const float* ugru_whh = (const float*)d_in[16];
    const float* ugru_bih = (const float*)d_in[17];
    const float* ugru_bhh = (const float*)d_in[18];
    float* out = (float*)d_out;

    k0<<<584, 256>>>(ex, su, ex_graph, W_ex, tgru_whh, fpart_w);
    k2<<<304, 256>>>(h, tgru_wih, tgru_bih, tgru_bhh, kc_gamma, W_kc,
                     fpart_w, fpart_b, ulin_w, ugru_wih, ugru_whh);
    dim3 g3(4, 32);
    k3<<<g3, 256>>>(ugru_bih, ugru_bhh, ulin_b, out);
}